// round 13
// baseline (speedup 1.0000x reference)
#include <cuda_runtime.h>
#include <cuda_fp16.h>
#include <stdint.h>
#include <math.h>

#define BATCH   8
#define LSEQ    4096
#define INDIM   256
#define DMODEL  512
#define OUTDIM  256
#define ML      (BATCH*LSEQ)      /* 32768 */
#define CHUNK   32
#define NCH     (LSEQ/CHUNK)      /* 128 */
#define K2      1280              /* xr(512) + xi(512) + inp(256) */
#define BK      32
#define PAD     40                /* padded smem row, fp16 elems (80 B) */
#define STAGES  4
#define ABYTES  (128*PAD*2)       /* 10240 B per operand tile (128-row) */
#define STG_BYTES (2*ABYTES)
#define GEMM_SMEM (STAGES*STG_BYTES)    /* 81920 B */
#define ABYTES64 (64*PAD*2)       /* 5120 B per operand tile (64-row) */
#define STG64    (2*ABYTES64)
#define GEMM64_SMEM (STAGES*STG64)      /* 40960 B */

// ---------------- device scratch -------------------------------------------
__device__ __align__(16) __half2 g_u[(size_t)ML*DMODEL];     // 64 MB (fp16 complex u)
__device__ __align__(16) float2 g_x[(size_t)ML*DMODEL];      // fallback
__device__ __align__(16) float2 g_carry[(size_t)BATCH*NCH*DMODEL];
__device__ float2 g_A[DMODEL];
__device__ float2 g_Ac[DMODEL];
__device__ __align__(16) __half g_X2[(size_t)ML*K2];         // 80 MB (fp16 activations)
__device__ __align__(16) __half g_W1[1024*256];              // fp16 weights
__device__ __align__(16) __half g_W2[256*K2];

__device__ __forceinline__ float2 cmul(float2 a, float2 b) {
    return make_float2(a.x*b.x - a.y*b.y, a.x*b.y + a.y*b.x);
}
__device__ __forceinline__ float2 cmad(float2 a, float2 b, float2 c) {
    // a*b + c
    return make_float2(fmaf(a.x, b.x, fmaf(-a.y, b.y, c.x)),
                       fmaf(a.x, b.y, fmaf( a.y, b.x, c.y)));
}

// ---------------- PTX helpers ------------------------------------------------
__device__ __forceinline__ uint32_t smem_u32(const void* p) {
    uint32_t a;
    asm("{ .reg .u64 t; cvta.to.shared.u64 t, %1; cvt.u32.u64 %0, t; }" : "=r"(a) : "l"(p));
    return a;
}
__device__ __forceinline__ void cp16(uint32_t dst, const void* src) {
    asm volatile("cp.async.cg.shared.global [%0], [%1], 16;" :: "r"(dst), "l"(src));
}
#define CP_COMMIT()  asm volatile("cp.async.commit_group;")
#define CP_WAIT2()   asm volatile("cp.async.wait_group 2;")
#define CP_WAIT0()   asm volatile("cp.async.wait_group 0;")

#define LDSM4(r, addr) \
    asm volatile("ldmatrix.sync.aligned.m8n8.x4.shared.b16 {%0,%1,%2,%3}, [%4];" \
        : "=r"((r)[0]),"=r"((r)[1]),"=r"((r)[2]),"=r"((r)[3]) : "r"(addr))

__device__ __forceinline__ void mma16816(float* c, const uint32_t* a, const uint32_t* b) {
    asm volatile("mma.sync.aligned.m16n8k16.row.col.f32.f16.f16.f32 "
        "{%0,%1,%2,%3}, {%4,%5,%6,%7}, {%8,%9}, {%0,%1,%2,%3};"
        : "+f"(c[0]), "+f"(c[1]), "+f"(c[2]), "+f"(c[3])
        : "r"(a[0]),"r"(a[1]),"r"(a[2]),"r"(a[3]), "r"(b[0]),"r"(b[1]));
}

// ---------------- fused prep: conv(4096) | W1(512) | W2(1280) | A(2) ---------
__global__ void prep_all_kernel(const float* __restrict__ inp,
                                const float* __restrict__ nu_log,
                                const float* __restrict__ theta_log,
                                const float* __restrict__ gamma_log,
                                const float* __restrict__ B_re,
                                const float* __restrict__ B_im,
                                const float* __restrict__ C_re,
                                const float* __restrict__ C_im,
                                const float* __restrict__ Dw) {
    int bid = blockIdx.x;
    int t = threadIdx.x;
    if (bid < 4096) {                                   // conv inputs -> X2 fp16
        int i = bid*256 + t;
        int m = i >> 5, h8 = (i & 31) << 3;
        const float4* src = (const float4*)(inp + (size_t)m*INDIM + h8);
        float4 v0 = src[0], v1 = src[1];
        float vals[8] = {v0.x, v0.y, v0.z, v0.w, v1.x, v1.y, v1.z, v1.w};
        __half hv[8];
        #pragma unroll
        for (int j = 0; j < 8; j++) hv[j] = __float2half_rn(vals[j]);
        *(uint4*)(g_X2 + (size_t)m*K2 + 1024 + h8) = *(uint4*)hv;
    } else if (bid < 4096 + 512) {                      // W1
        int i = (bid - 4096)*256 + t;                   // d*256 + h
        int d = i >> 8, h = i & 255;
        float s = expf(gamma_log[d]);
        g_W1[(size_t)(2*d)*256   + h] = __float2half_rn(B_re[i]*s);
        g_W1[(size_t)(2*d+1)*256 + h] = __float2half_rn(B_im[i]*s);
    } else if (bid < 4096 + 512 + 1280) {               // W2
        int i = (bid - 4608)*256 + t;                   // n*K2 + k
        int n = i / K2, k = i % K2;
        float v;
        if      (k < 512)  v =  C_re[(size_t)n*512 + k];
        else if (k < 1024) v = -C_im[(size_t)n*512 + (k-512)];
        else               v =  Dw  [(size_t)n*256 + (k-1024)];
        g_W2[i] = __float2half_rn(v);
    } else {                                            // A
        int d = (bid - 5888)*256 + t;
        if (d >= DMODEL) return;
        float r  = expf(-expf(nu_log[d]));
        float th = expf(theta_log[d]);
        float2 A = make_float2(r*cosf(th), r*sinf(th));
        g_A[d] = A;
        float2 p = make_float2(1.f, 0.f);
        #pragma unroll 8
        for (int i2 = 0; i2 < CHUNK; i2++) p = cmul(p, A);
        g_Ac[d] = p;                                    // A^CHUNK = A^32
    }
}

// ---------------- G1: 128x128 tiles, u = inputs x W1^T + fused pass1 --------
__device__ __forceinline__ void issue_loads128(
    int t, uint32_t sbase, int stg, int c,
    const __half* Aw, long lda,
    const __half* Bw, long ldb,
    int mBase, int nBase)
{
    long koff = (long)c * BK;
    uint32_t aBuf = sbase + stg*STG_BYTES;
    uint32_t bBuf = aBuf + ABYTES;
    #pragma unroll
    for (int r = 0; r < 2; r++) {
        int ci = t + r*256; int row = ci >> 2, j = ci & 3;
        cp16(aBuf + row*(PAD*2) + j*16, Aw + (size_t)(mBase+row)*lda + koff + j*8);
        cp16(bBuf + row*(PAD*2) + j*16, Bw + (size_t)(nBase+row)*ldb + koff + j*8);
    }
    CP_COMMIT();
}

__global__ __launch_bounds__(256, 2)
void gemm_g1_kernel() {
    const __half* Aw = g_X2 + 1024;  const long lda = K2;
    const __half* Bw = g_W1;         const long ldb = 256;
    const int NC = 256 / BK;         // 8
    const int t = threadIdx.x;
    const int wid = t >> 5, lane = t & 31;
    const int warp_m = wid & 3, warp_n = wid >> 2;
    const int mBase = blockIdx.y * 128;
    const int nBase = blockIdx.x * 128;

    extern __shared__ __align__(16) char smem[];
    uint32_t sbase = smem_u32(smem);

    float acc[2][8][4];
    #pragma unroll
    for (int mi = 0; mi < 2; mi++)
        #pragma unroll
        for (int ni = 0; ni < 8; ni++)
            #pragma unroll
            for (int q = 0; q < 4; q++) acc[mi][ni][q] = 0.f;

    uint32_t a_off[2], b_off[4];
    #pragma unroll
    for (int mi = 0; mi < 2; mi++) {
        int row = warp_m*32 + mi*16 + (lane & 15);
        int col = (lane >> 4) << 3;
        a_off[mi] = (uint32_t)((row*PAD + col) * 2);
    }
    #pragma unroll
    for (int p = 0; p < 4; p++) {
        int nrow = warp_n*64 + p*16 + (lane & 7) + ((lane >> 4) << 3);
        int col  = ((lane >> 3) & 1) << 3;
        b_off[p] = (uint32_t)((nrow*PAD + col) * 2);
    }

    issue_loads128(t, sbase, 0, 0, Aw, lda, Bw, ldb, mBase, nBase);
    issue_loads128(t, sbase, 1, 1, Aw, lda, Bw, ldb, mBase, nBase);
    issue_loads128(t, sbase, 2, 2, Aw, lda, Bw, ldb, mBase, nBase);

    for (int c = 0; c < NC; c++) {
        int stg = c & 3;
        CP_WAIT2();
        __syncthreads();
        if (c + 3 < NC)
            issue_loads128(t, sbase, (c+3) & 3, c+3, Aw, lda, Bw, ldb, mBase, nBase);
        else
            CP_COMMIT();

        uint32_t baseA = sbase + stg*STG_BYTES, baseB = baseA + ABYTES;
        #pragma unroll
        for (int ks = 0; ks < 2; ks++) {
            uint32_t afr[2][4], bfr[4][4];
            #pragma unroll
            for (int mi = 0; mi < 2; mi++) LDSM4(afr[mi], baseA + a_off[mi] + ks*32);
            #pragma unroll
            for (int p = 0; p < 4; p++)    LDSM4(bfr[p],  baseB + b_off[p]  + ks*32);
            #pragma unroll
            for (int mi = 0; mi < 2; mi++)
                #pragma unroll
                for (int ni = 0; ni < 8; ni++)
                    mma16816(acc[mi][ni], afr[mi], &bfr[ni >> 1][(ni & 1) * 2]);
        }
    }
    CP_WAIT0();
    __syncthreads();                   // pipeline smem dead; reuse for u tile

    // u epilogue: write gmem (half2) AND stash tile in smem for fused pass1
    __half2* us = (__half2*)smem;      // [128 rows][64 complex d] = 32 KB
    #pragma unroll
    for (int mi = 0; mi < 2; mi++) {
        int rl = warp_m*32 + mi*16 + (lane >> 2);       // local row
        int r0 = mBase + rl;
        #pragma unroll
        for (int ni = 0; ni < 8; ni++) {
            int col = warp_n*64 + ni*8 + (lane & 3)*2;  // local real col (even)
            int cl = col >> 1;                          // local complex d
            __half2 h0 = __floats2half2_rn(acc[mi][ni][0], acc[mi][ni][1]);
            __half2 h1 = __floats2half2_rn(acc[mi][ni][2], acc[mi][ni][3]);
            g_u[(size_t)r0*DMODEL + (nBase>>1) + cl]     = h0;
            g_u[(size_t)(r0+8)*DMODEL + (nBase>>1) + cl] = h1;
            us[rl*64 + cl]     = h0;
            us[(rl+8)*64 + cl] = h1;
        }
    }
    __syncthreads();

    // fused pass1: 4 chunks x 64 d's = 256 scan tasks
    {
        int dl = t & 63, c = t >> 6;
        int dglob = (nBase >> 1) + dl;
        float2 A = g_A[dglob];
        float2 x = make_float2(0.f, 0.f);
        const __half2* up = us + (c*32)*64 + dl;
        #pragma unroll 4
        for (int s = 0; s < 32; s++) {
            float2 u = __half22float2(up[s*64]);
            x = cmad(A, x, u);
        }
        int m = mBase + c*32;
        int b = m >> 12;                    // LSEQ = 4096
        int ch = (m & 4095) >> 5;           // CHUNK = 32
        g_carry[((size_t)b*NCH + ch)*DMODEL + dglob] = x;
    }
}

// ---------------- G2: 64x64 tiles, f32-accum mma ----------------------------
__device__ __forceinline__ void issue_loads64(
    int t, uint32_t sbase, int stg, int c,
    int mBase, int nBase)
{
    long koff = (long)c * BK;
    uint32_t aBuf = sbase + stg*STG64;
    uint32_t bBuf = aBuf + ABYTES64;
    int row = t >> 2, j = t & 3;
    cp16(aBuf + row*(PAD*2) + j*16, g_X2 + (size_t)(mBase+row)*K2 + koff + j*8);
    cp16(bBuf + row*(PAD*2) + j*16, g_W2 + (size_t)(nBase+row)*K2 + koff + j*8);
    CP_COMMIT();
}

__global__ __launch_bounds__(256, 2)
void gemm_g2_kernel(float* __restrict__ yout, int pair) {
    const int NC = K2 / BK;          // 40
    const int t = threadIdx.x;
    const int wid = t >> 5, lane = t & 31;
    const int warp_m = wid & 3, warp_n = wid >> 2;   // warp tile 16x32
    const int mBase = blockIdx.y * 64;
    const int nBase = blockIdx.x * 64;

    extern __shared__ __align__(16) char smem[];
    uint32_t sbase = smem_u32(smem);

    float acc[4][4];
    #pragma unroll
    for (int ni = 0; ni < 4; ni++)
        #pragma unroll
        for (int q = 0; q < 4; q++) acc[ni][q] = 0.f;

    uint32_t a_off, b_off[2];
    {
        int row = warp_m*16 + (lane & 15);
        int col = (lane >> 4) << 3;
        a_off = (uint32_t)((row*PAD + col) * 2);
    }
    #pragma unroll
    for (int p = 0; p < 2; p++) {
        int nrow = warp_n*32 + p*16 + (lane & 7) + ((lane >> 4) << 3);
        int col  = ((lane >> 3) & 1) << 3;
        b_off[p] = (uint32_t)((nrow*PAD + col) * 2);
    }

    issue_loads64(t, sbase, 0, 0, mBase, nBase);
    issue_loads64(t, sbase, 1, 1, mBase, nBase);
    issue_loads64(t, sbase, 2, 2, mBase, nBase);

    for (int c = 0; c < NC; c++) {
        int stg = c & 3;
        CP_WAIT2();
        __syncthreads();
        if (c + 3 < NC)
            issue_loads64(t, sbase, (c+3) & 3, c+3, mBase, nBase);
        else
            CP_COMMIT();

        uint32_t baseA = sbase + stg*STG64, baseB = baseA + ABYTES64;
        #pragma unroll
        for (int ks = 0; ks < 2; ks++) {
            uint32_t afr[4], bfr[2][4];
            LDSM4(afr, baseA + a_off + ks*32);
            #pragma unroll
            for (int p = 0; p < 2; p++) LDSM4(bfr[p], baseB + b_off[p] + ks*32);
            #pragma unroll
            for (int ni = 0; ni < 4; ni++)
                mma16816(acc[ni], afr, &bfr[ni >> 1][(ni & 1) * 2]);
        }
    }
    CP_WAIT0();

    int r0 = mBase + warp_m*16 + (lane >> 2);
    if (pair) {
        #pragma unroll
        for (int ni = 0; ni < 4; ni++) {
            int col = nBase + warp_n*32 + ni*8 + (lane & 3)*2;
            *(float4*)(yout + 2*((size_t)r0*256 + col)) =
                make_float4(acc[ni][0], 0.f, acc[ni][1], 0.f);
            *(float4*)(yout + 2*((size_t)(r0+8)*256 + col)) =
                make_float4(acc[ni][2], 0.f, acc[ni][3], 0.f);
        }
    } else {
        #pragma unroll
        for (int ni = 0; ni < 4; ni++) {
            int col = nBase + warp_n*32 + ni*8 + (lane & 3)*2;
            *(float2*)(yout + (size_t)r0*256 + col)     = make_float2(acc[ni][0], acc[ni][1]);
            *(float2*)(yout + (size_t)(r0+8)*256 + col) = make_float2(acc[ni][2], acc[ni][3]);
        }
    }
}

// ---------------- pass2: smem-staged Kogge-Stone over 128 chunks -------------
// Block handles (b, 8 consecutive d). Gmem accesses in 64B segments via smem.
__global__ __launch_bounds__(256)
void scan_pass2_kernel() {
    __shared__ float2 sc[8][NCH];                      // [d_local][ch], 8 KB
    int b  = blockIdx.x >> 6;                          // 512 blocks
    int d0 = (blockIdx.x & 63) << 3;
    int t = threadIdx.x;
    for (int i = t; i < 8*NCH; i += 256) {
        int ch = i >> 3, dl = i & 7;
        sc[dl][ch] = g_carry[((size_t)b*NCH + ch)*DMODEL + d0 + dl];
    }
    __syncthreads();
    int w = t >> 5, lane = t & 31;
    float2 Ac = g_Ac[d0 + w];                          // A^32
    float2 c0 = sc[w][4*lane];
    float2 c1 = sc[w][4*lane+1];
    float2 c2 = sc[w][4*lane+2];
    float2 c3 = sc[w][4*lane+3];
    float2 v = cmad(Ac, cmad(Ac, cmad(Ac, c0, c1), c2), c3);
    float2 w2 = cmul(Ac, Ac);
    float2 wk = cmul(w2, w2);                          // Ac^4 per-group step
    #pragma unroll
    for (int off = 1; off < 32; off <<= 1) {
        float2 pv;
        pv.x = __shfl_up_sync(0xFFFFFFFFu, v.x, off);
        pv.y = __shfl_up_sync(0xFFFFFFFFu, v.y, off);
        if (lane >= off) v = cmad(wk, pv, v);
        wk = cmul(wk, wk);
    }
    float2 prev;
    prev.x = __shfl_up_sync(0xFFFFFFFFu, v.x, 1);
    prev.y = __shfl_up_sync(0xFFFFFFFFu, v.y, 1);
    if (lane == 0) prev = make_float2(0.f, 0.f);
    float2 e0 = prev;
    float2 e1 = cmad(Ac, e0, c0);
    float2 e2 = cmad(Ac, e1, c1);
    float2 e3 = cmad(Ac, e2, c2);
    sc[w][4*lane]   = e0;
    sc[w][4*lane+1] = e1;
    sc[w][4*lane+2] = e2;
    sc[w][4*lane+3] = e3;
    __syncthreads();
    for (int i = t; i < 8*NCH; i += 256) {
        int ch = i >> 3, dl = i & 7;
        g_carry[((size_t)b*NCH + ch)*DMODEL + d0 + dl] = sc[dl][ch];
    }
}

// ---------------- pass3 ------------------------------------------------------
__global__ __launch_bounds__(256)
void scan_pass3_kernel(float2* __restrict__ xext, int use_ext, float* __restrict__ xreal) {
    int tid = blockIdx.x*blockDim.x + threadIdx.x;   // 131072 threads
    int dg = tid & 127;
    int ch = (tid >> 7) & (NCH-1);
    int b  = tid >> 14;
    if (b >= BATCH) return;
    int d = dg << 2;
    float2 A[4], x[4];
    #pragma unroll
    for (int q = 0; q < 4; q++) A[q] = g_A[d+q];
    {
        const float4* cr = (const float4*)(g_carry + ((size_t)b*NCH + ch)*DMODEL + d);
        float4 c0 = cr[0], c1 = cr[1];
        x[0] = make_float2(c0.x,c0.y); x[1] = make_float2(c0.z,c0.w);
        x[2] = make_float2(c1.x,c1.y); x[3] = make_float2(c1.z,c1.w);
    }
    int m0 = b*LSEQ + ch*CHUNK;
    size_t base = (size_t)m0*DMODEL + d;
    const __half2* up = g_u + base;
    float4* xo = (float4*)((use_ext ? xext : g_x) + base);
    #pragma unroll 4
    for (int s = 0; s < CHUNK; s++) {
        float4 raw = *(const float4*)up;
        const __half2* hp = (const __half2*)&raw;
        #pragma unroll
        for (int q = 0; q < 4; q++) {
            float2 u = __half22float2(hp[q]);
            x[q] = cmad(A[q], x[q], u);
        }
        xo[0] = make_float4(x[0].x, x[0].y, x[1].x, x[1].y);
        xo[1] = make_float4(x[2].x, x[2].y, x[3].x, x[3].y);
        if (xreal)
            *(float4*)(xreal + base + (size_t)s*DMODEL) =
                make_float4(x[0].x, x[1].x, x[2].x, x[3].x);
        size_t xrow = (size_t)(m0 + s)*K2;
        __half hr[4], hi_[4];
        #pragma unroll
        for (int q = 0; q < 4; q++) {
            hr[q]  = __float2half_rn(x[q].x);
            hi_[q] = __float2half_rn(x[q].y);
        }
        *(uint2*)(g_X2 + xrow + d)       = *(uint2*)hr;
        *(uint2*)(g_X2 + xrow + 512 + d) = *(uint2*)hi_;
        up += DMODEL;
        xo += DMODEL/2;
    }
}

// ---------------- host -------------------------------------------------------
extern "C" void kernel_launch(void* const* d_in, const int* in_sizes, int n_in,
                              void* d_out, int out_size) {
    const float* inputs    = (const float*)d_in[0];
    const float* nu_log    = (const float*)d_in[1];
    const float* theta_log = (const float*)d_in[2];
    const float* gamma_log = (const float*)d_in[3];
    const float* B_re      = (const float*)d_in[4];
    const float* B_im      = (const float*)d_in[5];
    const float* C_re      = (const float*)d_in[6];
    const float* C_im      = (const float*)d_in[7];
    const float* Dw        = (const float*)d_in[8];
    float* outF = (float*)d_out;

    const long long X = (long long)ML*DMODEL;
    const long long Y = (long long)ML*OUTDIM;
    float2* xext = 0; int use_ext = 0; float* xreal = 0;
    float* yout = 0; int pair = 0;
    long long os = (long long)out_size;
    if      (os == 2*X + Y)   { xext = (float2*)d_out; use_ext = 1; yout = outF + 2*X; }
    else if (os == 2*X + 2*Y) { xext = (float2*)d_out; use_ext = 1; yout = outF + 2*X; pair = 1; }
    else if (os == X + Y)     { xreal = outF; yout = outF + X; }
    else if (os == Y)         { yout = outF; }
    else if (os == 2*X)       { xext = (float2*)d_out; use_ext = 1; }
    else                      { xext = (float2*)d_out; use_ext = 1; yout = outF + 2*X; pair = 1; }

    cudaFuncSetAttribute(gemm_g1_kernel,
                         cudaFuncAttributeMaxDynamicSharedMemorySize, GEMM_SMEM);
    cudaFuncSetAttribute(gemm_g2_kernel,
                         cudaFuncAttributeMaxDynamicSharedMemorySize, GEMM64_SMEM);

    // fused preps: conv(4096) | W1(512) | W2(1280) | A(2)
    prep_all_kernel<<<5890, 256>>>(inputs, nu_log, theta_log, gamma_log,
                                   B_re, B_im, C_re, C_im, Dw);

    // G1: u = inputs x W1^T (M=32768, N=1024, K=256) + fused chunk-carry scan
    gemm_g1_kernel<<<dim3(1024/128, ML/128), 256, GEMM_SMEM>>>();

    scan_pass2_kernel<<<BATCH*DMODEL/8, 256>>>();
    scan_pass3_kernel<<<(BATCH*NCH*DMODEL/4)/256, 256>>>(xext, use_ext, xreal);

    if (yout) {
        // G2: y = [xr|xi|inp] x [Cr|-Ci|D]^T  (M=32768, N=256, K=1280), 64x64 tiles
        gemm_g2_kernel<<<dim3(256/64, ML/64), 256, GEMM64_SMEM>>>(yout, pair);
    }
}

// round 14
// speedup vs baseline: 1.0367x; 1.0367x over previous
#include <cuda_runtime.h>
#include <cuda_fp16.h>
#include <stdint.h>
#include <math.h>

#define BATCH   8
#define LSEQ    4096
#define INDIM   256
#define DMODEL  512
#define OUTDIM  256
#define ML      (BATCH*LSEQ)      /* 32768 */
#define CHUNK   32
#define NCH     (LSEQ/CHUNK)      /* 128 */
#define K2      1280              /* xr(512) + xi(512) + inp(256) */
#define BK      32
#define PAD     40                /* padded smem row, fp16 elems (80 B) */
#define STAGES  4
#define ABYTES  (128*PAD*2)       /* 10240 B per operand tile (128-row) */
#define STG_BYTES (2*ABYTES)
#define GEMM_SMEM (STAGES*STG_BYTES)    /* 81920 B */
#define ABYTES64 (64*PAD*2)       /* 5120 B per operand tile (64-row) */
#define STG64    (2*ABYTES64)
#define GEMM64_SMEM (STAGES*STG64)      /* 40960 B */

// ---------------- device scratch -------------------------------------------
__device__ __align__(16) __half2 g_u[(size_t)ML*DMODEL];     // 64 MB (fp16 complex u)
__device__ __align__(16) float2 g_x[(size_t)ML*DMODEL];      // fallback
__device__ __align__(16) float2 g_carry[(size_t)BATCH*NCH*DMODEL];
__device__ float2 g_A[DMODEL];
__device__ float2 g_Ac[DMODEL];
__device__ __align__(16) __half g_X2[(size_t)ML*K2];         // 80 MB (fp16 activations)
__device__ __align__(16) __half g_W1[1024*256];              // fp16 weights
__device__ __align__(16) __half g_W2[256*K2];

__device__ __forceinline__ float2 cmul(float2 a, float2 b) {
    return make_float2(a.x*b.x - a.y*b.y, a.x*b.y + a.y*b.x);
}
__device__ __forceinline__ float2 cmad(float2 a, float2 b, float2 c) {
    // a*b + c
    return make_float2(fmaf(a.x, b.x, fmaf(-a.y, b.y, c.x)),
                       fmaf(a.x, b.y, fmaf( a.y, b.x, c.y)));
}

// ---------------- PTX helpers ------------------------------------------------
__device__ __forceinline__ uint32_t smem_u32(const void* p) {
    uint32_t a;
    asm("{ .reg .u64 t; cvta.to.shared.u64 t, %1; cvt.u32.u64 %0, t; }" : "=r"(a) : "l"(p));
    return a;
}
__device__ __forceinline__ void cp16(uint32_t dst, const void* src) {
    asm volatile("cp.async.cg.shared.global [%0], [%1], 16;" :: "r"(dst), "l"(src));
}
#define CP_COMMIT()  asm volatile("cp.async.commit_group;")
#define CP_WAIT2()   asm volatile("cp.async.wait_group 2;")
#define CP_WAIT0()   asm volatile("cp.async.wait_group 0;")

#define LDSM4(r, addr) \
    asm volatile("ldmatrix.sync.aligned.m8n8.x4.shared.b16 {%0,%1,%2,%3}, [%4];" \
        : "=r"((r)[0]),"=r"((r)[1]),"=r"((r)[2]),"=r"((r)[3]) : "r"(addr))

__device__ __forceinline__ void mma16816(float* c, const uint32_t* a, const uint32_t* b) {
    asm volatile("mma.sync.aligned.m16n8k16.row.col.f32.f16.f16.f32 "
        "{%0,%1,%2,%3}, {%4,%5,%6,%7}, {%8,%9}, {%0,%1,%2,%3};"
        : "+f"(c[0]), "+f"(c[1]), "+f"(c[2]), "+f"(c[3])
        : "r"(a[0]),"r"(a[1]),"r"(a[2]),"r"(a[3]), "r"(b[0]),"r"(b[1]));
}

// ---------------- fused prep: conv(4096) | W1(512) | W2(1280) | A(2) ---------
__global__ void prep_all_kernel(const float* __restrict__ inp,
                                const float* __restrict__ nu_log,
                                const float* __restrict__ theta_log,
                                const float* __restrict__ gamma_log,
                                const float* __restrict__ B_re,
                                const float* __restrict__ B_im,
                                const float* __restrict__ C_re,
                                const float* __restrict__ C_im,
                                const float* __restrict__ Dw) {
    int bid = blockIdx.x;
    int t = threadIdx.x;
    if (bid < 4096) {                                   // conv inputs -> X2 fp16
        int i = bid*256 + t;
        int m = i >> 5, h8 = (i & 31) << 3;
        const float4* src = (const float4*)(inp + (size_t)m*INDIM + h8);
        float4 v0 = src[0], v1 = src[1];
        float vals[8] = {v0.x, v0.y, v0.z, v0.w, v1.x, v1.y, v1.z, v1.w};
        __half hv[8];
        #pragma unroll
        for (int j = 0; j < 8; j++) hv[j] = __float2half_rn(vals[j]);
        *(uint4*)(g_X2 + (size_t)m*K2 + 1024 + h8) = *(uint4*)hv;
    } else if (bid < 4096 + 512) {                      // W1
        int i = (bid - 4096)*256 + t;                   // d*256 + h
        int d = i >> 8, h = i & 255;
        float s = expf(gamma_log[d]);
        g_W1[(size_t)(2*d)*256   + h] = __float2half_rn(B_re[i]*s);
        g_W1[(size_t)(2*d+1)*256 + h] = __float2half_rn(B_im[i]*s);
    } else if (bid < 4096 + 512 + 1280) {               // W2
        int i = (bid - 4608)*256 + t;                   // n*K2 + k
        int n = i / K2, k = i % K2;
        float v;
        if      (k < 512)  v =  C_re[(size_t)n*512 + k];
        else if (k < 1024) v = -C_im[(size_t)n*512 + (k-512)];
        else               v =  Dw  [(size_t)n*256 + (k-1024)];
        g_W2[i] = __float2half_rn(v);
    } else {                                            // A
        int d = (bid - 5888)*256 + t;
        if (d >= DMODEL) return;
        float r  = expf(-expf(nu_log[d]));
        float th = expf(theta_log[d]);
        float2 A = make_float2(r*cosf(th), r*sinf(th));
        g_A[d] = A;
        float2 p = make_float2(1.f, 0.f);
        #pragma unroll 8
        for (int i2 = 0; i2 < CHUNK; i2++) p = cmul(p, A);
        g_Ac[d] = p;                                    // A^CHUNK = A^32
    }
}

// ---------------- G1: 128x128 tiles, u = inputs x W1^T ----------------------
__device__ __forceinline__ void issue_loads128(
    int t, uint32_t sbase, int stg, int c,
    const __half* Aw, long lda,
    const __half* Bw, long ldb,
    int mBase, int nBase)
{
    long koff = (long)c * BK;
    uint32_t aBuf = sbase + stg*STG_BYTES;
    uint32_t bBuf = aBuf + ABYTES;
    #pragma unroll
    for (int r = 0; r < 2; r++) {
        int ci = t + r*256; int row = ci >> 2, j = ci & 3;
        cp16(aBuf + row*(PAD*2) + j*16, Aw + (size_t)(mBase+row)*lda + koff + j*8);
        cp16(bBuf + row*(PAD*2) + j*16, Bw + (size_t)(nBase+row)*ldb + koff + j*8);
    }
    CP_COMMIT();
}

__global__ __launch_bounds__(256, 2)
void gemm_g1_kernel() {
    const __half* Aw = g_X2 + 1024;  const long lda = K2;
    const __half* Bw = g_W1;         const long ldb = 256;
    const int NC = 256 / BK;         // 8
    const int t = threadIdx.x;
    const int wid = t >> 5, lane = t & 31;
    const int warp_m = wid & 3, warp_n = wid >> 2;
    const int mBase = blockIdx.y * 128;
    const int nBase = blockIdx.x * 128;

    extern __shared__ __align__(16) char smem[];
    uint32_t sbase = smem_u32(smem);

    float acc[2][8][4];
    #pragma unroll
    for (int mi = 0; mi < 2; mi++)
        #pragma unroll
        for (int ni = 0; ni < 8; ni++)
            #pragma unroll
            for (int q = 0; q < 4; q++) acc[mi][ni][q] = 0.f;

    uint32_t a_off[2], b_off[4];
    #pragma unroll
    for (int mi = 0; mi < 2; mi++) {
        int row = warp_m*32 + mi*16 + (lane & 15);
        int col = (lane >> 4) << 3;
        a_off[mi] = (uint32_t)((row*PAD + col) * 2);
    }
    #pragma unroll
    for (int p = 0; p < 4; p++) {
        int nrow = warp_n*64 + p*16 + (lane & 7) + ((lane >> 4) << 3);
        int col  = ((lane >> 3) & 1) << 3;
        b_off[p] = (uint32_t)((nrow*PAD + col) * 2);
    }

    issue_loads128(t, sbase, 0, 0, Aw, lda, Bw, ldb, mBase, nBase);
    issue_loads128(t, sbase, 1, 1, Aw, lda, Bw, ldb, mBase, nBase);
    issue_loads128(t, sbase, 2, 2, Aw, lda, Bw, ldb, mBase, nBase);

    for (int c = 0; c < NC; c++) {
        int stg = c & 3;
        CP_WAIT2();
        __syncthreads();
        if (c + 3 < NC)
            issue_loads128(t, sbase, (c+3) & 3, c+3, Aw, lda, Bw, ldb, mBase, nBase);
        else
            CP_COMMIT();

        uint32_t baseA = sbase + stg*STG_BYTES, baseB = baseA + ABYTES;
        #pragma unroll
        for (int ks = 0; ks < 2; ks++) {
            uint32_t afr[2][4], bfr[4][4];
            #pragma unroll
            for (int mi = 0; mi < 2; mi++) LDSM4(afr[mi], baseA + a_off[mi] + ks*32);
            #pragma unroll
            for (int p = 0; p < 4; p++)    LDSM4(bfr[p],  baseB + b_off[p]  + ks*32);
            #pragma unroll
            for (int mi = 0; mi < 2; mi++)
                #pragma unroll
                for (int ni = 0; ni < 8; ni++)
                    mma16816(acc[mi][ni], afr[mi], &bfr[ni >> 1][(ni & 1) * 2]);
        }
    }
    CP_WAIT0();

    // u epilogue: fp16 complex (half2 per element)
    #pragma unroll
    for (int mi = 0; mi < 2; mi++) {
        int r0 = mBase + warp_m*32 + mi*16 + (lane >> 2);
        #pragma unroll
        for (int ni = 0; ni < 8; ni++) {
            int col = nBase + warp_n*64 + ni*8 + (lane & 3)*2;   // even
            g_u[(size_t)r0*DMODEL + (col >> 1)] =
                __floats2half2_rn(acc[mi][ni][0], acc[mi][ni][1]);
            g_u[(size_t)(r0+8)*DMODEL + (col >> 1)] =
                __floats2half2_rn(acc[mi][ni][2], acc[mi][ni][3]);
        }
    }
}

// ---------------- G2: 64x64 tiles, f32-accum mma ----------------------------
__device__ __forceinline__ void issue_loads64(
    int t, uint32_t sbase, int stg, int c,
    int mBase, int nBase)
{
    long koff = (long)c * BK;
    uint32_t aBuf = sbase + stg*STG64;
    uint32_t bBuf = aBuf + ABYTES64;
    int row = t >> 2, j = t & 3;
    cp16(aBuf + row*(PAD*2) + j*16, g_X2 + (size_t)(mBase+row)*K2 + koff + j*8);
    cp16(bBuf + row*(PAD*2) + j*16, g_W2 + (size_t)(nBase+row)*K2 + koff + j*8);
    CP_COMMIT();
}

__global__ __launch_bounds__(256, 2)
void gemm_g2_kernel(float* __restrict__ yout, int pair) {
    const int NC = K2 / BK;          // 40
    const int t = threadIdx.x;
    const int wid = t >> 5, lane = t & 31;
    const int warp_m = wid & 3, warp_n = wid >> 2;   // warp tile 16x32
    const int mBase = blockIdx.y * 64;
    const int nBase = blockIdx.x * 64;

    extern __shared__ __align__(16) char smem[];
    uint32_t sbase = smem_u32(smem);

    float acc[4][4];
    #pragma unroll
    for (int ni = 0; ni < 4; ni++)
        #pragma unroll
        for (int q = 0; q < 4; q++) acc[ni][q] = 0.f;

    uint32_t a_off, b_off[2];
    {
        int row = warp_m*16 + (lane & 15);
        int col = (lane >> 4) << 3;
        a_off = (uint32_t)((row*PAD + col) * 2);
    }
    #pragma unroll
    for (int p = 0; p < 2; p++) {
        int nrow = warp_n*32 + p*16 + (lane & 7) + ((lane >> 4) << 3);
        int col  = ((lane >> 3) & 1) << 3;
        b_off[p] = (uint32_t)((nrow*PAD + col) * 2);
    }

    issue_loads64(t, sbase, 0, 0, mBase, nBase);
    issue_loads64(t, sbase, 1, 1, mBase, nBase);
    issue_loads64(t, sbase, 2, 2, mBase, nBase);

    for (int c = 0; c < NC; c++) {
        int stg = c & 3;
        CP_WAIT2();
        __syncthreads();
        if (c + 3 < NC)
            issue_loads64(t, sbase, (c+3) & 3, c+3, mBase, nBase);
        else
            CP_COMMIT();

        uint32_t baseA = sbase + stg*STG64, baseB = baseA + ABYTES64;
        #pragma unroll
        for (int ks = 0; ks < 2; ks++) {
            uint32_t afr[4], bfr[2][4];
            LDSM4(afr, baseA + a_off + ks*32);
            #pragma unroll
            for (int p = 0; p < 2; p++) LDSM4(bfr[p], baseB + b_off[p] + ks*32);
            #pragma unroll
            for (int ni = 0; ni < 4; ni++)
                mma16816(acc[ni], afr, &bfr[ni >> 1][(ni & 1) * 2]);
        }
    }
    CP_WAIT0();

    int r0 = mBase + warp_m*16 + (lane >> 2);
    if (pair) {
        #pragma unroll
        for (int ni = 0; ni < 4; ni++) {
            int col = nBase + warp_n*32 + ni*8 + (lane & 3)*2;
            *(float4*)(yout + 2*((size_t)r0*256 + col)) =
                make_float4(acc[ni][0], 0.f, acc[ni][1], 0.f);
            *(float4*)(yout + 2*((size_t)(r0+8)*256 + col)) =
                make_float4(acc[ni][2], 0.f, acc[ni][3], 0.f);
        }
    } else {
        #pragma unroll
        for (int ni = 0; ni < 4; ni++) {
            int col = nBase + warp_n*32 + ni*8 + (lane & 3)*2;
            *(float2*)(yout + (size_t)r0*256 + col)     = make_float2(acc[ni][0], acc[ni][1]);
            *(float2*)(yout + (size_t)(r0+8)*256 + col) = make_float2(acc[ni][2], acc[ni][3]);
        }
    }
}

// ---------------- chunked parallel scan (CHUNK=32, NCH=128) ------------------
__global__ __launch_bounds__(256)
void scan_pass1_kernel() {
    int tid = blockIdx.x*blockDim.x + threadIdx.x;   // 131072 threads
    int dg = tid & 127;
    int ch = (tid >> 7) & (NCH-1);
    int b  = tid >> 14;
    if (b >= BATCH) return;
    int d = dg << 2;
    float2 A[4], x[4];
    #pragma unroll
    for (int q = 0; q < 4; q++) { A[q] = g_A[d+q]; x[q] = make_float2(0.f, 0.f); }
    const __half2* up = g_u + ((size_t)(b*LSEQ + ch*CHUNK))*DMODEL + d;
    #pragma unroll 4
    for (int s = 0; s < CHUNK; s++) {
        float4 raw = *(const float4*)up;             // 4 half2 complexes (16B)
        const __half2* hp = (const __half2*)&raw;
        #pragma unroll
        for (int q = 0; q < 4; q++) {
            float2 u = __half22float2(hp[q]);
            x[q] = cmad(A[q], x[q], u);
        }
        up += DMODEL;
    }
    float4* cr = (float4*)(g_carry + ((size_t)b*NCH + ch)*DMODEL + d);
    cr[0] = make_float4(x[0].x, x[0].y, x[1].x, x[1].y);
    cr[1] = make_float4(x[2].x, x[2].y, x[3].x, x[3].y);
}

// ---------------- pass2: smem-staged Kogge-Stone over 128 chunks -------------
// Block handles (b, 8 consecutive d). Gmem accesses in 64B segments via smem.
__global__ __launch_bounds__(256)
void scan_pass2_kernel() {
    __shared__ float2 sc[8][NCH];                      // [d_local][ch], 8 KB
    int b  = blockIdx.x >> 6;                          // 512 blocks
    int d0 = (blockIdx.x & 63) << 3;
    int t = threadIdx.x;
    for (int i = t; i < 8*NCH; i += 256) {
        int ch = i >> 3, dl = i & 7;
        sc[dl][ch] = g_carry[((size_t)b*NCH + ch)*DMODEL + d0 + dl];
    }
    __syncthreads();
    int w = t >> 5, lane = t & 31;
    float2 Ac = g_Ac[d0 + w];                          // A^32
    float2 c0 = sc[w][4*lane];
    float2 c1 = sc[w][4*lane+1];
    float2 c2 = sc[w][4*lane+2];
    float2 c3 = sc[w][4*lane+3];
    float2 v = cmad(Ac, cmad(Ac, cmad(Ac, c0, c1), c2), c3);
    float2 w2 = cmul(Ac, Ac);
    float2 wk = cmul(w2, w2);                          // Ac^4 per-group step
    #pragma unroll
    for (int off = 1; off < 32; off <<= 1) {
        float2 pv;
        pv.x = __shfl_up_sync(0xFFFFFFFFu, v.x, off);
        pv.y = __shfl_up_sync(0xFFFFFFFFu, v.y, off);
        if (lane >= off) v = cmad(wk, pv, v);
        wk = cmul(wk, wk);
    }
    float2 prev;
    prev.x = __shfl_up_sync(0xFFFFFFFFu, v.x, 1);
    prev.y = __shfl_up_sync(0xFFFFFFFFu, v.y, 1);
    if (lane == 0) prev = make_float2(0.f, 0.f);
    float2 e0 = prev;
    float2 e1 = cmad(Ac, e0, c0);
    float2 e2 = cmad(Ac, e1, c1);
    float2 e3 = cmad(Ac, e2, c2);
    sc[w][4*lane]   = e0;
    sc[w][4*lane+1] = e1;
    sc[w][4*lane+2] = e2;
    sc[w][4*lane+3] = e3;
    __syncthreads();
    for (int i = t; i < 8*NCH; i += 256) {
        int ch = i >> 3, dl = i & 7;
        g_carry[((size_t)b*NCH + ch)*DMODEL + d0 + dl] = sc[dl][ch];
    }
}

// ---------------- pass3 ------------------------------------------------------
__global__ __launch_bounds__(256)
void scan_pass3_kernel(float2* __restrict__ xext, int use_ext, float* __restrict__ xreal) {
    int tid = blockIdx.x*blockDim.x + threadIdx.x;   // 131072 threads
    int dg = tid & 127;
    int ch = (tid >> 7) & (NCH-1);
    int b  = tid >> 14;
    if (b >= BATCH) return;
    int d = dg << 2;
    float2 A[4], x[4];
    #pragma unroll
    for (int q = 0; q < 4; q++) A[q] = g_A[d+q];
    {
        const float4* cr = (const float4*)(g_carry + ((size_t)b*NCH + ch)*DMODEL + d);
        float4 c0 = cr[0], c1 = cr[1];
        x[0] = make_float2(c0.x,c0.y); x[1] = make_float2(c0.z,c0.w);
        x[2] = make_float2(c1.x,c1.y); x[3] = make_float2(c1.z,c1.w);
    }
    int m0 = b*LSEQ + ch*CHUNK;
    size_t base = (size_t)m0*DMODEL + d;
    const __half2* up = g_u + base;
    float4* xo = (float4*)((use_ext ? xext : g_x) + base);
    #pragma unroll 4
    for (int s = 0; s < CHUNK; s++) {
        float4 raw = *(const float4*)up;
        const __half2* hp = (const __half2*)&raw;
        #pragma unroll
        for (int q = 0; q < 4; q++) {
            float2 u = __half22float2(hp[q]);
            x[q] = cmad(A[q], x[q], u);
        }
        xo[0] = make_float4(x[0].x, x[0].y, x[1].x, x[1].y);
        xo[1] = make_float4(x[2].x, x[2].y, x[3].x, x[3].y);
        if (xreal)
            *(float4*)(xreal + base + (size_t)s*DMODEL) =
                make_float4(x[0].x, x[1].x, x[2].x, x[3].x);
        size_t xrow = (size_t)(m0 + s)*K2;
        __half hr[4], hi_[4];
        #pragma unroll
        for (int q = 0; q < 4; q++) {
            hr[q]  = __float2half_rn(x[q].x);
            hi_[q] = __float2half_rn(x[q].y);
        }
        *(uint2*)(g_X2 + xrow + d)       = *(uint2*)hr;
        *(uint2*)(g_X2 + xrow + 512 + d) = *(uint2*)hi_;
        up += DMODEL;
        xo += DMODEL/2;
    }
}

// ---------------- host -------------------------------------------------------
extern "C" void kernel_launch(void* const* d_in, const int* in_sizes, int n_in,
                              void* d_out, int out_size) {
    const float* inputs    = (const float*)d_in[0];
    const float* nu_log    = (const float*)d_in[1];
    const float* theta_log = (const float*)d_in[2];
    const float* gamma_log = (const float*)d_in[3];
    const float* B_re      = (const float*)d_in[4];
    const float* B_im      = (const float*)d_in[5];
    const float* C_re      = (const float*)d_in[6];
    const float* C_im      = (const float*)d_in[7];
    const float* Dw        = (const float*)d_in[8];
    float* outF = (float*)d_out;

    const long long X = (long long)ML*DMODEL;
    const long long Y = (long long)ML*OUTDIM;
    float2* xext = 0; int use_ext = 0; float* xreal = 0;
    float* yout = 0; int pair = 0;
    long long os = (long long)out_size;
    if      (os == 2*X + Y)   { xext = (float2*)d_out; use_ext = 1; yout = outF + 2*X; }
    else if (os == 2*X + 2*Y) { xext = (float2*)d_out; use_ext = 1; yout = outF + 2*X; pair = 1; }
    else if (os == X + Y)     { xreal = outF; yout = outF + X; }
    else if (os == Y)         { yout = outF; }
    else if (os == 2*X)       { xext = (float2*)d_out; use_ext = 1; }
    else                      { xext = (float2*)d_out; use_ext = 1; yout = outF + 2*X; pair = 1; }

    cudaFuncSetAttribute(gemm_g1_kernel,
                         cudaFuncAttributeMaxDynamicSharedMemorySize, GEMM_SMEM);
    cudaFuncSetAttribute(gemm_g2_kernel,
                         cudaFuncAttributeMaxDynamicSharedMemorySize, GEMM64_SMEM);

    // fused preps: conv(4096) | W1(512) | W2(1280) | A(2)
    prep_all_kernel<<<5890, 256>>>(inputs, nu_log, theta_log, gamma_log,
                                   B_re, B_im, C_re, C_im, Dw);

    // G1: u = inputs x W1^T  (M=32768, N=1024, K=256)
    gemm_g1_kernel<<<dim3(1024/128, ML/128), 256, GEMM_SMEM>>>();

    scan_pass1_kernel<<<(BATCH*NCH*DMODEL/4)/256, 256>>>();
    scan_pass2_kernel<<<BATCH*DMODEL/8, 256>>>();
    scan_pass3_kernel<<<(BATCH*NCH*DMODEL/4)/256, 256>>>(xext, use_ext, xreal);

    if (yout) {
        // G2: y = [xr|xi|inp] x [Cr|-Ci|D]^T  (M=32768, N=256, K=1280), 64x64 tiles
        gemm_g2_kernel<<<dim3(256/64, ML/64), 256, GEMM64_SMEM>>>(yout, pair);
    }
}

// round 15
// speedup vs baseline: 1.0435x; 1.0066x over previous
#include <cuda_runtime.h>
#include <cuda_fp16.h>
#include <stdint.h>
#include <math.h>

#define BATCH   8
#define LSEQ    4096
#define INDIM   256
#define DMODEL  512
#define OUTDIM  256
#define ML      (BATCH*LSEQ)      /* 32768 */
#define CHUNK   32
#define NCH     (LSEQ/CHUNK)      /* 128 */
#define K2      1280              /* xr(512) + xi(512) + inp(256) */
#define BK      32
#define PAD     40                /* padded smem row, fp16 elems (80 B) */
#define STAGES  4
#define ABYTES  (128*PAD*2)       /* 10240 B per operand tile (128-row) */
#define STG_BYTES (2*ABYTES)
#define GEMM_SMEM (STAGES*STG_BYTES)    /* 81920 B */
#define ABYTES64 (64*PAD*2)       /* 5120 B per operand tile (64-row) */
#define STG64    (2*ABYTES64)
#define GEMM64_SMEM (STAGES*STG64)      /* 40960 B */

// ---------------- device scratch -------------------------------------------
__device__ __align__(16) __half2 g_u[(size_t)ML*DMODEL];     // 64 MB (fp16 complex u)
__device__ __align__(16) float2 g_x[(size_t)ML*DMODEL];      // fallback
__device__ __align__(16) float2 g_carry[(size_t)BATCH*NCH*DMODEL];
__device__ float2 g_A[DMODEL];
__device__ float2 g_Ac[DMODEL];
__device__ __align__(16) __half g_X2[(size_t)ML*K2];         // 80 MB (fp16 activations)
__device__ __align__(16) __half g_W1[1024*256];              // fp16 weights
__device__ __align__(16) __half g_W2[256*K2];

__device__ __forceinline__ float2 cmul(float2 a, float2 b) {
    return make_float2(a.x*b.x - a.y*b.y, a.x*b.y + a.y*b.x);
}
__device__ __forceinline__ float2 cmad(float2 a, float2 b, float2 c) {
    return make_float2(fmaf(a.x, b.x, fmaf(-a.y, b.y, c.x)),
                       fmaf(a.x, b.y, fmaf( a.y, b.x, c.y)));
}

// ---------------- PTX helpers ------------------------------------------------
__device__ __forceinline__ uint32_t smem_u32(const void* p) {
    uint32_t a;
    asm("{ .reg .u64 t; cvta.to.shared.u64 t, %1; cvt.u32.u64 %0, t; }" : "=r"(a) : "l"(p));
    return a;
}
__device__ __forceinline__ void cp16(uint32_t dst, const void* src) {
    asm volatile("cp.async.cg.shared.global [%0], [%1], 16;" :: "r"(dst), "l"(src));
}
#define CP_COMMIT()  asm volatile("cp.async.commit_group;")
#define CP_WAIT2()   asm volatile("cp.async.wait_group 2;")
#define CP_WAIT0()   asm volatile("cp.async.wait_group 0;")

#define LDSM4(r, addr) \
    asm volatile("ldmatrix.sync.aligned.m8n8.x4.shared.b16 {%0,%1,%2,%3}, [%4];" \
        : "=r"((r)[0]),"=r"((r)[1]),"=r"((r)[2]),"=r"((r)[3]) : "r"(addr))

__device__ __forceinline__ void mma16816(float* c, const uint32_t* a, const uint32_t* b) {
    asm volatile("mma.sync.aligned.m16n8k16.row.col.f32.f16.f16.f32 "
        "{%0,%1,%2,%3}, {%4,%5,%6,%7}, {%8,%9}, {%0,%1,%2,%3};"
        : "+f"(c[0]), "+f"(c[1]), "+f"(c[2]), "+f"(c[3])
        : "r"(a[0]),"r"(a[1]),"r"(a[2]),"r"(a[3]), "r"(b[0]),"r"(b[1]));
}
__device__ __forceinline__ void stcs4(float* p, float4 v) {
    asm volatile("st.global.cs.v4.f32 [%0], {%1,%2,%3,%4};"
        :: "l"(p), "f"(v.x), "f"(v.y), "f"(v.z), "f"(v.w) : "memory");
}
__device__ __forceinline__ void stcs2(float* p, float2 v) {
    asm volatile("st.global.cs.v2.f32 [%0], {%1,%2};"
        :: "l"(p), "f"(v.x), "f"(v.y) : "memory");
}

// ---------------- fused prep: conv(4096) | W1(512) | W2(1280) | A(2) ---------
__global__ void prep_all_kernel(const float* __restrict__ inp,
                                const float* __restrict__ nu_log,
                                const float* __restrict__ theta_log,
                                const float* __restrict__ gamma_log,
                                const float* __restrict__ B_re,
                                const float* __restrict__ B_im,
                                const float* __restrict__ C_re,
                                const float* __restrict__ C_im,
                                const float* __restrict__ Dw) {
    int bid = blockIdx.x;
    int t = threadIdx.x;
    if (bid < 4096) {                                   // conv inputs -> X2 fp16
        int i = bid*256 + t;
        int m = i >> 5, h8 = (i & 31) << 3;
        const float4* src = (const float4*)(inp + (size_t)m*INDIM + h8);
        float4 v0 = src[0], v1 = src[1];
        float vals[8] = {v0.x, v0.y, v0.z, v0.w, v1.x, v1.y, v1.z, v1.w};
        __half hv[8];
        #pragma unroll
        for (int j = 0; j < 8; j++) hv[j] = __float2half_rn(vals[j]);
        *(uint4*)(g_X2 + (size_t)m*K2 + 1024 + h8) = *(uint4*)hv;
    } else if (bid < 4096 + 512) {                      // W1
        int i = (bid - 4096)*256 + t;                   // d*256 + h
        int d = i >> 8, h = i & 255;
        float s = expf(gamma_log[d]);
        g_W1[(size_t)(2*d)*256   + h] = __float2half_rn(B_re[i]*s);
        g_W1[(size_t)(2*d+1)*256 + h] = __float2half_rn(B_im[i]*s);
    } else if (bid < 4096 + 512 + 1280) {               // W2
        int i = (bid - 4608)*256 + t;                   // n*K2 + k
        int n = i / K2, k = i % K2;
        float v;
        if      (k < 512)  v =  C_re[(size_t)n*512 + k];
        else if (k < 1024) v = -C_im[(size_t)n*512 + (k-512)];
        else               v =  Dw  [(size_t)n*256 + (k-1024)];
        g_W2[i] = __float2half_rn(v);
    } else {                                            // A
        int d = (bid - 5888)*256 + t;
        if (d >= DMODEL) return;
        float r  = expf(-expf(nu_log[d]));
        float th = expf(theta_log[d]);
        float2 A = make_float2(r*cosf(th), r*sinf(th));
        g_A[d] = A;
        float2 p = make_float2(1.f, 0.f);
        #pragma unroll 8
        for (int i2 = 0; i2 < CHUNK; i2++) p = cmul(p, A);
        g_Ac[d] = p;                                    // A^CHUNK = A^32
    }
}

// ---------------- G1: 128x128 tiles, u = inputs x W1^T ----------------------
__device__ __forceinline__ void issue_loads128(
    int t, uint32_t sbase, int stg, int c,
    const __half* Aw, long lda,
    const __half* Bw, long ldb,
    int mBase, int nBase)
{
    long koff = (long)c * BK;
    uint32_t aBuf = sbase + stg*STG_BYTES;
    uint32_t bBuf = aBuf + ABYTES;
    #pragma unroll
    for (int r = 0; r < 2; r++) {
        int ci = t + r*256; int row = ci >> 2, j = ci & 3;
        cp16(aBuf + row*(PAD*2) + j*16, Aw + (size_t)(mBase+row)*lda + koff + j*8);
        cp16(bBuf + row*(PAD*2) + j*16, Bw + (size_t)(nBase+row)*ldb + koff + j*8);
    }
    CP_COMMIT();
}

__global__ __launch_bounds__(256, 2)
void gemm_g1_kernel() {
    const __half* Aw = g_X2 + 1024;  const long lda = K2;
    const __half* Bw = g_W1;         const long ldb = 256;
    const int NC = 256 / BK;         // 8
    const int t = threadIdx.x;
    const int wid = t >> 5, lane = t & 31;
    const int warp_m = wid & 3, warp_n = wid >> 2;
    const int mBase = blockIdx.y * 128;
    const int nBase = blockIdx.x * 128;

    extern __shared__ __align__(16) char smem[];
    uint32_t sbase = smem_u32(smem);

    float acc[2][8][4];
    #pragma unroll
    for (int mi = 0; mi < 2; mi++)
        #pragma unroll
        for (int ni = 0; ni < 8; ni++)
            #pragma unroll
            for (int q = 0; q < 4; q++) acc[mi][ni][q] = 0.f;

    uint32_t a_off[2], b_off[4];
    #pragma unroll
    for (int mi = 0; mi < 2; mi++) {
        int row = warp_m*32 + mi*16 + (lane & 15);
        int col = (lane >> 4) << 3;
        a_off[mi] = (uint32_t)((row*PAD + col) * 2);
    }
    #pragma unroll
    for (int p = 0; p < 4; p++) {
        int nrow = warp_n*64 + p*16 + (lane & 7) + ((lane >> 4) << 3);
        int col  = ((lane >> 3) & 1) << 3;
        b_off[p] = (uint32_t)((nrow*PAD + col) * 2);
    }

    issue_loads128(t, sbase, 0, 0, Aw, lda, Bw, ldb, mBase, nBase);
    issue_loads128(t, sbase, 1, 1, Aw, lda, Bw, ldb, mBase, nBase);
    issue_loads128(t, sbase, 2, 2, Aw, lda, Bw, ldb, mBase, nBase);

    for (int c = 0; c < NC; c++) {
        int stg = c & 3;
        CP_WAIT2();
        __syncthreads();
        if (c + 3 < NC)
            issue_loads128(t, sbase, (c+3) & 3, c+3, Aw, lda, Bw, ldb, mBase, nBase);
        else
            CP_COMMIT();

        uint32_t baseA = sbase + stg*STG_BYTES, baseB = baseA + ABYTES;
        #pragma unroll
        for (int ks = 0; ks < 2; ks++) {
            uint32_t afr[2][4], bfr[4][4];
            #pragma unroll
            for (int mi = 0; mi < 2; mi++) LDSM4(afr[mi], baseA + a_off[mi] + ks*32);
            #pragma unroll
            for (int p = 0; p < 4; p++)    LDSM4(bfr[p],  baseB + b_off[p]  + ks*32);
            #pragma unroll
            for (int mi = 0; mi < 2; mi++)
                #pragma unroll
                for (int ni = 0; ni < 8; ni++)
                    mma16816(acc[mi][ni], afr[mi], &bfr[ni >> 1][(ni & 1) * 2]);
        }
    }
    CP_WAIT0();

    // u epilogue: fp16 complex (half2 per element)
    #pragma unroll
    for (int mi = 0; mi < 2; mi++) {
        int r0 = mBase + warp_m*32 + mi*16 + (lane >> 2);
        #pragma unroll
        for (int ni = 0; ni < 8; ni++) {
            int col = nBase + warp_n*64 + ni*8 + (lane & 3)*2;   // even
            g_u[(size_t)r0*DMODEL + (col >> 1)] =
                __floats2half2_rn(acc[mi][ni][0], acc[mi][ni][1]);
            g_u[(size_t)(r0+8)*DMODEL + (col >> 1)] =
                __floats2half2_rn(acc[mi][ni][2], acc[mi][ni][3]);
        }
    }
}

// ---------------- G2: 64x64 tiles, f32-accum mma ----------------------------
__device__ __forceinline__ void issue_loads64(
    int t, uint32_t sbase, int stg, int c,
    int mBase, int nBase)
{
    long koff = (long)c * BK;
    uint32_t aBuf = sbase + stg*STG64;
    uint32_t bBuf = aBuf + ABYTES64;
    int row = t >> 2, j = t & 3;
    cp16(aBuf + row*(PAD*2) + j*16, g_X2 + (size_t)(mBase+row)*K2 + koff + j*8);
    cp16(bBuf + row*(PAD*2) + j*16, g_W2 + (size_t)(nBase+row)*K2 + koff + j*8);
    CP_COMMIT();
}

__global__ __launch_bounds__(256, 2)
void gemm_g2_kernel(float* __restrict__ yout, int pair) {
    const int NC = K2 / BK;          // 40
    const int t = threadIdx.x;
    const int wid = t >> 5, lane = t & 31;
    const int warp_m = wid & 3, warp_n = wid >> 2;   // warp tile 16x32
    const int mBase = blockIdx.y * 64;
    const int nBase = blockIdx.x * 64;

    extern __shared__ __align__(16) char smem[];
    uint32_t sbase = smem_u32(smem);

    float acc[4][4];
    #pragma unroll
    for (int ni = 0; ni < 4; ni++)
        #pragma unroll
        for (int q = 0; q < 4; q++) acc[ni][q] = 0.f;

    uint32_t a_off, b_off[2];
    {
        int row = warp_m*16 + (lane & 15);
        int col = (lane >> 4) << 3;
        a_off = (uint32_t)((row*PAD + col) * 2);
    }
    #pragma unroll
    for (int p = 0; p < 2; p++) {
        int nrow = warp_n*32 + p*16 + (lane & 7) + ((lane >> 4) << 3);
        int col  = ((lane >> 3) & 1) << 3;
        b_off[p] = (uint32_t)((nrow*PAD + col) * 2);
    }

    issue_loads64(t, sbase, 0, 0, mBase, nBase);
    issue_loads64(t, sbase, 1, 1, mBase, nBase);
    issue_loads64(t, sbase, 2, 2, mBase, nBase);

    for (int c = 0; c < NC; c++) {
        int stg = c & 3;
        CP_WAIT2();
        __syncthreads();
        if (c + 3 < NC)
            issue_loads64(t, sbase, (c+3) & 3, c+3, mBase, nBase);
        else
            CP_COMMIT();

        uint32_t baseA = sbase + stg*STG64, baseB = baseA + ABYTES64;
        #pragma unroll
        for (int ks = 0; ks < 2; ks++) {
            uint32_t afr[4], bfr[2][4];
            LDSM4(afr, baseA + a_off + ks*32);
            #pragma unroll
            for (int p = 0; p < 2; p++) LDSM4(bfr[p], baseB + b_off[p] + ks*32);
            #pragma unroll
            for (int ni = 0; ni < 4; ni++)
                mma16816(acc[ni], afr, &bfr[ni >> 1][(ni & 1) * 2]);
        }
    }
    CP_WAIT0();

    int r0 = mBase + warp_m*16 + (lane >> 2);
    if (pair) {
        #pragma unroll
        for (int ni = 0; ni < 4; ni++) {
            int col = nBase + warp_n*32 + ni*8 + (lane & 3)*2;
            *(float4*)(yout + 2*((size_t)r0*256 + col)) =
                make_float4(acc[ni][0], 0.f, acc[ni][1], 0.f);
            *(float4*)(yout + 2*((size_t)(r0+8)*256 + col)) =
                make_float4(acc[ni][2], 0.f, acc[ni][3], 0.f);
        }
    } else {
        #pragma unroll
        for (int ni = 0; ni < 4; ni++) {
            int col = nBase + warp_n*32 + ni*8 + (lane & 3)*2;
            *(float2*)(yout + (size_t)r0*256 + col)     = make_float2(acc[ni][0], acc[ni][1]);
            *(float2*)(yout + (size_t)(r0+8)*256 + col) = make_float2(acc[ni][2], acc[ni][3]);
        }
    }
}

// ---------------- chunked parallel scan (2 d's per thread) -------------------
__global__ __launch_bounds__(256)
void scan_pass1_kernel() {
    int tid = blockIdx.x*blockDim.x + threadIdx.x;   // 262144 threads
    int dg = tid & 255;
    int ch = (tid >> 8) & (NCH-1);
    int b  = tid >> 15;
    if (b >= BATCH) return;
    int d = dg << 1;
    float2 A[2], x[2];
    #pragma unroll
    for (int q = 0; q < 2; q++) { A[q] = g_A[d+q]; x[q] = make_float2(0.f, 0.f); }
    const __half2* up = g_u + ((size_t)(b*LSEQ + ch*CHUNK))*DMODEL + d;
    #pragma unroll 8
    for (int s = 0; s < CHUNK; s++) {
        float2 raw = *(const float2*)up;             // 2 half2 complexes (8B)
        const __half2* hp = (const __half2*)&raw;
        #pragma unroll
        for (int q = 0; q < 2; q++) {
            float2 u = __half22float2(hp[q]);
            x[q] = cmad(A[q], x[q], u);
        }
        up += DMODEL;
    }
    *(float4*)(g_carry + ((size_t)b*NCH + ch)*DMODEL + d) =
        make_float4(x[0].x, x[0].y, x[1].x, x[1].y);
}

// ---------------- pass2: smem-staged Kogge-Stone over 128 chunks -------------
__global__ __launch_bounds__(256)
void scan_pass2_kernel() {
    __shared__ float2 sc[8][NCH];                      // [d_local][ch], 8 KB
    int b  = blockIdx.x >> 6;                          // 512 blocks
    int d0 = (blockIdx.x & 63) << 3;
    int t = threadIdx.x;
    for (int i = t; i < 8*NCH; i += 256) {
        int ch = i >> 3, dl = i & 7;
        sc[dl][ch] = g_carry[((size_t)b*NCH + ch)*DMODEL + d0 + dl];
    }
    __syncthreads();
    int w = t >> 5, lane = t & 31;
    float2 Ac = g_Ac[d0 + w];                          // A^32
    float2 c0 = sc[w][4*lane];
    float2 c1 = sc[w][4*lane+1];
    float2 c2 = sc[w][4*lane+2];
    float2 c3 = sc[w][4*lane+3];
    float2 v = cmad(Ac, cmad(Ac, cmad(Ac, c0, c1), c2), c3);
    float2 w2 = cmul(Ac, Ac);
    float2 wk = cmul(w2, w2);                          // Ac^4 per-group step
    #pragma unroll
    for (int off = 1; off < 32; off <<= 1) {
        float2 pv;
        pv.x = __shfl_up_sync(0xFFFFFFFFu, v.x, off);
        pv.y = __shfl_up_sync(0xFFFFFFFFu, v.y, off);
        if (lane >= off) v = cmad(wk, pv, v);
        wk = cmul(wk, wk);
    }
    float2 prev;
    prev.x = __shfl_up_sync(0xFFFFFFFFu, v.x, 1);
    prev.y = __shfl_up_sync(0xFFFFFFFFu, v.y, 1);
    if (lane == 0) prev = make_float2(0.f, 0.f);
    float2 e0 = prev;
    float2 e1 = cmad(Ac, e0, c0);
    float2 e2 = cmad(Ac, e1, c1);
    float2 e3 = cmad(Ac, e2, c2);
    sc[w][4*lane]   = e0;
    sc[w][4*lane+1] = e1;
    sc[w][4*lane+2] = e2;
    sc[w][4*lane+3] = e3;
    __syncthreads();
    for (int i = t; i < 8*NCH; i += 256) {
        int ch = i >> 3, dl = i & 7;
        g_carry[((size_t)b*NCH + ch)*DMODEL + d0 + dl] = sc[dl][ch];
    }
}

// ---------------- pass3: 2 d's per thread, streaming x stores ----------------
__global__ __launch_bounds__(256)
void scan_pass3_kernel(float2* __restrict__ xext, int use_ext, float* __restrict__ xreal) {
    int tid = blockIdx.x*blockDim.x + threadIdx.x;   // 262144 threads
    int dg = tid & 255;
    int ch = (tid >> 8) & (NCH-1);
    int b  = tid >> 15;
    if (b >= BATCH) return;
    int d = dg << 1;
    float2 A[2], x[2];
    #pragma unroll
    for (int q = 0; q < 2; q++) A[q] = g_A[d+q];
    {
        float4 c0 = *(const float4*)(g_carry + ((size_t)b*NCH + ch)*DMODEL + d);
        x[0] = make_float2(c0.x, c0.y);
        x[1] = make_float2(c0.z, c0.w);
    }
    int m0 = b*LSEQ + ch*CHUNK;
    size_t base = (size_t)m0*DMODEL + d;
    const __half2* up = g_u + base;
    float* xo = (float*)((use_ext ? xext : g_x) + base);
    #pragma unroll 8
    for (int s = 0; s < CHUNK; s++) {
        float2 raw = *(const float2*)up;
        const __half2* hp = (const __half2*)&raw;
        #pragma unroll
        for (int q = 0; q < 2; q++) {
            float2 u = __half22float2(hp[q]);
            x[q] = cmad(A[q], x[q], u);
        }
        stcs4(xo, make_float4(x[0].x, x[0].y, x[1].x, x[1].y));
        if (xreal)
            stcs2(xreal + base + (size_t)s*DMODEL, make_float2(x[0].x, x[1].x));
        size_t xrow = (size_t)(m0 + s)*K2;
        __half2 hr = __floats2half2_rn(x[0].x, x[1].x);
        __half2 hi_ = __floats2half2_rn(x[0].y, x[1].y);
        *(__half2*)(g_X2 + xrow + d)       = hr;
        *(__half2*)(g_X2 + xrow + 512 + d) = hi_;
        up += DMODEL;
        xo += 2*DMODEL;
    }
}

// ---------------- host -------------------------------------------------------
extern "C" void kernel_launch(void* const* d_in, const int* in_sizes, int n_in,
                              void* d_out, int out_size) {
    const float* inputs    = (const float*)d_in[0];
    const float* nu_log    = (const float*)d_in[1];
    const float* theta_log = (const float*)d_in[2];
    const float* gamma_log = (const float*)d_in[3];
    const float* B_re      = (const float*)d_in[4];
    const float* B_im      = (const float*)d_in[5];
    const float* C_re      = (const float*)d_in[6];
    const float* C_im      = (const float*)d_in[7];
    const float* Dw        = (const float*)d_in[8];
    float* outF = (float*)d_out;

    const long long X = (long long)ML*DMODEL;
    const long long Y = (long long)ML*OUTDIM;
    float2* xext = 0; int use_ext = 0; float* xreal = 0;
    float* yout = 0; int pair = 0;
    long long os = (long long)out_size;
    if      (os == 2*X + Y)   { xext = (float2*)d_out; use_ext = 1; yout = outF + 2*X; }
    else if (os == 2*X + 2*Y) { xext = (float2*)d_out; use_ext = 1; yout = outF + 2*X; pair = 1; }
    else if (os == X + Y)     { xreal = outF; yout = outF + X; }
    else if (os == Y)         { yout = outF; }
    else if (os == 2*X)       { xext = (float2*)d_out; use_ext = 1; }
    else                      { xext = (float2*)d_out; use_ext = 1; yout = outF + 2*X; pair = 1; }

    cudaFuncSetAttribute(gemm_g1_kernel,
                         cudaFuncAttributeMaxDynamicSharedMemorySize, GEMM_SMEM);
    cudaFuncSetAttribute(gemm_g2_kernel,
                         cudaFuncAttributeMaxDynamicSharedMemorySize, GEMM64_SMEM);

    // fused preps: conv(4096) | W1(512) | W2(1280) | A(2)
    prep_all_kernel<<<5890, 256>>>(inputs, nu_log, theta_log, gamma_log,
                                   B_re, B_im, C_re, C_im, Dw);

    // G1: u = inputs x W1^T  (M=32768, N=1024, K=256)
    gemm_g1_kernel<<<dim3(1024/128, ML/128), 256, GEMM_SMEM>>>();

    scan_pass1_kernel<<<(BATCH*NCH*DMODEL/2)/256, 256>>>();
    scan_pass2_kernel<<<BATCH*DMODEL/8, 256>>>();
    scan_pass3_kernel<<<(BATCH*NCH*DMODEL/2)/256, 256>>>(xext, use_ext, xreal);

    if (yout) {
        // G2: y = [xr|xi|inp] x [Cr|-Ci|D]^T  (M=32768, N=256, K=1280), 64x64 tiles
        gemm_g2_kernel<<<dim3(256/64, ML/64), 256, GEMM64_SMEM>>>(yout, pair);
    }
}

// round 16
// speedup vs baseline: 1.0446x; 1.0010x over previous
#include <cuda_runtime.h>
#include <cuda_fp16.h>
#include <stdint.h>
#include <math.h>

#define BATCH   8
#define LSEQ    4096
#define INDIM   256
#define DMODEL  512
#define OUTDIM  256
#define ML      (BATCH*LSEQ)      /* 32768 */
#define CHUNK   32
#define NCH     (LSEQ/CHUNK)      /* 128 */
#define K2      1280              /* x interleaved re/im (1024) + inp(256) */
#define BK      32
#define PAD     40                /* padded smem row, fp16 elems (80 B) */
#define STAGES  4
#define ABYTES  (128*PAD*2)       /* 10240 B per operand tile (128-row) */
#define STG_BYTES (2*ABYTES)
#define GEMM_SMEM (STAGES*STG_BYTES)    /* 81920 B */
#define ABYTES64 (64*PAD*2)       /* 5120 B per operand tile (64-row) */
#define STG64    (2*ABYTES64)
#define GEMM64_SMEM (STAGES*STG64)      /* 40960 B */

// ---------------- device scratch -------------------------------------------
__device__ __align__(16) __half2 g_u[(size_t)ML*DMODEL];     // 64 MB (fp16 complex u)
__device__ __align__(16) float2 g_x[(size_t)ML*DMODEL];      // fallback
__device__ __align__(16) float2 g_carry[(size_t)BATCH*NCH*DMODEL];
__device__ float2 g_A[DMODEL];
__device__ float2 g_Ac[DMODEL];
__device__ __align__(16) __half g_X2[(size_t)ML*K2];         // 80 MB (fp16 activations)
__device__ __align__(16) __half g_W1[1024*256];              // fp16 weights
__device__ __align__(16) __half g_W2[256*K2];

__device__ __forceinline__ float2 cmul(float2 a, float2 b) {
    return make_float2(a.x*b.x - a.y*b.y, a.x*b.y + a.y*b.x);
}
__device__ __forceinline__ float2 cmad(float2 a, float2 b, float2 c) {
    return make_float2(fmaf(a.x, b.x, fmaf(-a.y, b.y, c.x)),
                       fmaf(a.x, b.y, fmaf( a.y, b.x, c.y)));
}

// ---------------- PTX helpers ------------------------------------------------
__device__ __forceinline__ uint32_t smem_u32(const void* p) {
    uint32_t a;
    asm("{ .reg .u64 t; cvta.to.shared.u64 t, %1; cvt.u32.u64 %0, t; }" : "=r"(a) : "l"(p));
    return a;
}
__device__ __forceinline__ void cp16(uint32_t dst, const void* src) {
    asm volatile("cp.async.cg.shared.global [%0], [%1], 16;" :: "r"(dst), "l"(src));
}
#define CP_COMMIT()  asm volatile("cp.async.commit_group;")
#define CP_WAIT2()   asm volatile("cp.async.wait_group 2;")
#define CP_WAIT0()   asm volatile("cp.async.wait_group 0;")

#define LDSM4(r, addr) \
    asm volatile("ldmatrix.sync.aligned.m8n8.x4.shared.b16 {%0,%1,%2,%3}, [%4];" \
        : "=r"((r)[0]),"=r"((r)[1]),"=r"((r)[2]),"=r"((r)[3]) : "r"(addr))

__device__ __forceinline__ void mma16816(float* c, const uint32_t* a, const uint32_t* b) {
    asm volatile("mma.sync.aligned.m16n8k16.row.col.f32.f16.f16.f32 "
        "{%0,%1,%2,%3}, {%4,%5,%6,%7}, {%8,%9}, {%0,%1,%2,%3};"
        : "+f"(c[0]), "+f"(c[1]), "+f"(c[2]), "+f"(c[3])
        : "r"(a[0]),"r"(a[1]),"r"(a[2]),"r"(a[3]), "r"(b[0]),"r"(b[1]));
}
__device__ __forceinline__ void stcs4(float* p, float4 v) {
    asm volatile("st.global.cs.v4.f32 [%0], {%1,%2,%3,%4};"
        :: "l"(p), "f"(v.x), "f"(v.y), "f"(v.z), "f"(v.w) : "memory");
}
__device__ __forceinline__ void stcs2(float* p, float2 v) {
    asm volatile("st.global.cs.v2.f32 [%0], {%1,%2};"
        :: "l"(p), "f"(v.x), "f"(v.y) : "memory");
}

// ---------------- fused prep: conv(4096) | W1(512) | W2(1280) | A(2) ---------
__global__ void prep_all_kernel(const float* __restrict__ inp,
                                const float* __restrict__ nu_log,
                                const float* __restrict__ theta_log,
                                const float* __restrict__ gamma_log,
                                const float* __restrict__ B_re,
                                const float* __restrict__ B_im,
                                const float* __restrict__ C_re,
                                const float* __restrict__ C_im,
                                const float* __restrict__ Dw) {
    int bid = blockIdx.x;
    int t = threadIdx.x;
    if (bid < 4096) {                                   // conv inputs -> X2 fp16
        int i = bid*256 + t;
        int m = i >> 5, h8 = (i & 31) << 3;
        const float4* src = (const float4*)(inp + (size_t)m*INDIM + h8);
        float4 v0 = src[0], v1 = src[1];
        float vals[8] = {v0.x, v0.y, v0.z, v0.w, v1.x, v1.y, v1.z, v1.w};
        __half hv[8];
        #pragma unroll
        for (int j = 0; j < 8; j++) hv[j] = __float2half_rn(vals[j]);
        *(uint4*)(g_X2 + (size_t)m*K2 + 1024 + h8) = *(uint4*)hv;
    } else if (bid < 4096 + 512) {                      // W1
        int i = (bid - 4096)*256 + t;                   // d*256 + h
        int d = i >> 8, h = i & 255;
        float s = expf(gamma_log[d]);
        g_W1[(size_t)(2*d)*256   + h] = __float2half_rn(B_re[i]*s);
        g_W1[(size_t)(2*d+1)*256 + h] = __float2half_rn(B_im[i]*s);
    } else if (bid < 4096 + 512 + 1280) {               // W2 (x part INTERLEAVED)
        int i = (bid - 4608)*256 + t;                   // n*K2 + k
        int n = i / K2, k = i % K2;
        float v;
        if (k < 1024) {                                 // interleaved Cr/-Ci
            int j = k >> 1;
            v = (k & 1) ? -C_im[(size_t)n*512 + j] : C_re[(size_t)n*512 + j];
        } else {
            v = Dw[(size_t)n*256 + (k-1024)];
        }
        g_W2[i] = __float2half_rn(v);
    } else {                                            // A
        int d = (bid - 5888)*256 + t;
        if (d >= DMODEL) return;
        float r  = expf(-expf(nu_log[d]));
        float th = expf(theta_log[d]);
        float2 A = make_float2(r*cosf(th), r*sinf(th));
        g_A[d] = A;
        float2 p = make_float2(1.f, 0.f);
        #pragma unroll 8
        for (int i2 = 0; i2 < CHUNK; i2++) p = cmul(p, A);
        g_Ac[d] = p;                                    // A^CHUNK = A^32
    }
}

// ---------------- G1: 128x128 tiles, u = inputs x W1^T ----------------------
__device__ __forceinline__ void issue_loads128(
    int t, uint32_t sbase, int stg, int c,
    const __half* Aw, long lda,
    const __half* Bw, long ldb,
    int mBase, int nBase)
{
    long koff = (long)c * BK;
    uint32_t aBuf = sbase + stg*STG_BYTES;
    uint32_t bBuf = aBuf + ABYTES;
    #pragma unroll
    for (int r = 0; r < 2; r++) {
        int ci = t + r*256; int row = ci >> 2, j = ci & 3;
        cp16(aBuf + row*(PAD*2) + j*16, Aw + (size_t)(mBase+row)*lda + koff + j*8);
        cp16(bBuf + row*(PAD*2) + j*16, Bw + (size_t)(nBase+row)*ldb + koff + j*8);
    }
    CP_COMMIT();
}

__global__ __launch_bounds__(256, 2)
void gemm_g1_kernel() {
    const __half* Aw = g_X2 + 1024;  const long lda = K2;
    const __half* Bw = g_W1;         const long ldb = 256;
    const int NC = 256 / BK;         // 8
    const int t = threadIdx.x;
    const int wid = t >> 5, lane = t & 31;
    const int warp_m = wid & 3, warp_n = wid >> 2;
    const int mBase = blockIdx.y * 128;
    const int nBase = blockIdx.x * 128;

    extern __shared__ __align__(16) char smem[];
    uint32_t sbase = smem_u32(smem);

    float acc[2][8][4];
    #pragma unroll
    for (int mi = 0; mi < 2; mi++)
        #pragma unroll
        for (int ni = 0; ni < 8; ni++)
            #pragma unroll
            for (int q = 0; q < 4; q++) acc[mi][ni][q] = 0.f;

    uint32_t a_off[2], b_off[4];
    #pragma unroll
    for (int mi = 0; mi < 2; mi++) {
        int row = warp_m*32 + mi*16 + (lane & 15);
        int col = (lane >> 4) << 3;
        a_off[mi] = (uint32_t)((row*PAD + col) * 2);
    }
    #pragma unroll
    for (int p = 0; p < 4; p++) {
        int nrow = warp_n*64 + p*16 + (lane & 7) + ((lane >> 4) << 3);
        int col  = ((lane >> 3) & 1) << 3;
        b_off[p] = (uint32_t)((nrow*PAD + col) * 2);
    }

    issue_loads128(t, sbase, 0, 0, Aw, lda, Bw, ldb, mBase, nBase);
    issue_loads128(t, sbase, 1, 1, Aw, lda, Bw, ldb, mBase, nBase);
    issue_loads128(t, sbase, 2, 2, Aw, lda, Bw, ldb, mBase, nBase);

    for (int c = 0; c < NC; c++) {
        int stg = c & 3;
        CP_WAIT2();
        __syncthreads();
        if (c + 3 < NC)
            issue_loads128(t, sbase, (c+3) & 3, c+3, Aw, lda, Bw, ldb, mBase, nBase);
        else
            CP_COMMIT();

        uint32_t baseA = sbase + stg*STG_BYTES, baseB = baseA + ABYTES;
        #pragma unroll
        for (int ks = 0; ks < 2; ks++) {
            uint32_t afr[2][4], bfr[4][4];
            #pragma unroll
            for (int mi = 0; mi < 2; mi++) LDSM4(afr[mi], baseA + a_off[mi] + ks*32);
            #pragma unroll
            for (int p = 0; p < 4; p++)    LDSM4(bfr[p],  baseB + b_off[p]  + ks*32);
            #pragma unroll
            for (int mi = 0; mi < 2; mi++)
                #pragma unroll
                for (int ni = 0; ni < 8; ni++)
                    mma16816(acc[mi][ni], afr[mi], &bfr[ni >> 1][(ni & 1) * 2]);
        }
    }
    CP_WAIT0();

    // u epilogue: fp16 complex (half2 per element)
    #pragma unroll
    for (int mi = 0; mi < 2; mi++) {
        int r0 = mBase + warp_m*32 + mi*16 + (lane >> 2);
        #pragma unroll
        for (int ni = 0; ni < 8; ni++) {
            int col = nBase + warp_n*64 + ni*8 + (lane & 3)*2;   // even
            g_u[(size_t)r0*DMODEL + (col >> 1)] =
                __floats2half2_rn(acc[mi][ni][0], acc[mi][ni][1]);
            g_u[(size_t)(r0+8)*DMODEL + (col >> 1)] =
                __floats2half2_rn(acc[mi][ni][2], acc[mi][ni][3]);
        }
    }
}

// ---------------- G2: 64x64 tiles, f32-accum mma ----------------------------
__device__ __forceinline__ void issue_loads64(
    int t, uint32_t sbase, int stg, int c,
    int mBase, int nBase)
{
    long koff = (long)c * BK;
    uint32_t aBuf = sbase + stg*STG64;
    uint32_t bBuf = aBuf + ABYTES64;
    int row = t >> 2, j = t & 3;
    cp16(aBuf + row*(PAD*2) + j*16, g_X2 + (size_t)(mBase+row)*K2 + koff + j*8);
    cp16(bBuf + row*(PAD*2) + j*16, g_W2 + (size_t)(nBase+row)*K2 + koff + j*8);
    CP_COMMIT();
}

__global__ __launch_bounds__(256, 2)
void gemm_g2_kernel(float* __restrict__ yout, int pair) {
    const int NC = K2 / BK;          // 40
    const int t = threadIdx.x;
    const int wid = t >> 5, lane = t & 31;
    const int warp_m = wid & 3, warp_n = wid >> 2;   // warp tile 16x32
    const int mBase = blockIdx.y * 64;
    const int nBase = blockIdx.x * 64;

    extern __shared__ __align__(16) char smem[];
    uint32_t sbase = smem_u32(smem);

    float acc[4][4];
    #pragma unroll
    for (int ni = 0; ni < 4; ni++)
        #pragma unroll
        for (int q = 0; q < 4; q++) acc[ni][q] = 0.f;

    uint32_t a_off, b_off[2];
    {
        int row = warp_m*16 + (lane & 15);
        int col = (lane >> 4) << 3;
        a_off = (uint32_t)((row*PAD + col) * 2);
    }
    #pragma unroll
    for (int p = 0; p < 2; p++) {
        int nrow = warp_n*32 + p*16 + (lane & 7) + ((lane >> 4) << 3);
        int col  = ((lane >> 3) & 1) << 3;
        b_off[p] = (uint32_t)((nrow*PAD + col) * 2);
    }

    issue_loads64(t, sbase, 0, 0, mBase, nBase);
    issue_loads64(t, sbase, 1, 1, mBase, nBase);
    issue_loads64(t, sbase, 2, 2, mBase, nBase);

    for (int c = 0; c < NC; c++) {
        int stg = c & 3;
        CP_WAIT2();
        __syncthreads();
        if (c + 3 < NC)
            issue_loads64(t, sbase, (c+3) & 3, c+3, mBase, nBase);
        else
            CP_COMMIT();

        uint32_t baseA = sbase + stg*STG64, baseB = baseA + ABYTES64;
        #pragma unroll
        for (int ks = 0; ks < 2; ks++) {
            uint32_t afr[4], bfr[2][4];
            LDSM4(afr, baseA + a_off + ks*32);
            #pragma unroll
            for (int p = 0; p < 2; p++) LDSM4(bfr[p], baseB + b_off[p] + ks*32);
            #pragma unroll
            for (int ni = 0; ni < 4; ni++)
                mma16816(acc[ni], afr, &bfr[ni >> 1][(ni & 1) * 2]);
        }
    }
    CP_WAIT0();

    int r0 = mBase + warp_m*16 + (lane >> 2);
    if (pair) {
        #pragma unroll
        for (int ni = 0; ni < 4; ni++) {
            int col = nBase + warp_n*32 + ni*8 + (lane & 3)*2;
            *(float4*)(yout + 2*((size_t)r0*256 + col)) =
                make_float4(acc[ni][0], 0.f, acc[ni][1], 0.f);
            *(float4*)(yout + 2*((size_t)(r0+8)*256 + col)) =
                make_float4(acc[ni][2], 0.f, acc[ni][3], 0.f);
        }
    } else {
        #pragma unroll
        for (int ni = 0; ni < 4; ni++) {
            int col = nBase + warp_n*32 + ni*8 + (lane & 3)*2;
            *(float2*)(yout + (size_t)r0*256 + col)     = make_float2(acc[ni][0], acc[ni][1]);
            *(float2*)(yout + (size_t)(r0+8)*256 + col) = make_float2(acc[ni][2], acc[ni][3]);
        }
    }
}

// ---------------- chunked parallel scan (2 d's per thread) -------------------
__global__ __launch_bounds__(256)
void scan_pass1_kernel() {
    int tid = blockIdx.x*blockDim.x + threadIdx.x;   // 262144 threads
    int dg = tid & 255;
    int ch = (tid >> 8) & (NCH-1);
    int b  = tid >> 15;
    if (b >= BATCH) return;
    int d = dg << 1;
    float2 A[2], x[2];
    #pragma unroll
    for (int q = 0; q < 2; q++) { A[q] = g_A[d+q]; x[q] = make_float2(0.f, 0.f); }
    const __half2* up = g_u + ((size_t)(b*LSEQ + ch*CHUNK))*DMODEL + d;
    #pragma unroll 8
    for (int s = 0; s < CHUNK; s++) {
        float2 raw = *(const float2*)up;             // 2 half2 complexes (8B)
        const __half2* hp = (const __half2*)&raw;
        #pragma unroll
        for (int q = 0; q < 2; q++) {
            float2 u = __half22float2(hp[q]);
            x[q] = cmad(A[q], x[q], u);
        }
        up += DMODEL;
    }
    *(float4*)(g_carry + ((size_t)b*NCH + ch)*DMODEL + d) =
        make_float4(x[0].x, x[0].y, x[1].x, x[1].y);
}

// ---------------- pass2: smem-staged Kogge-Stone over 128 chunks -------------
__global__ __launch_bounds__(256)
void scan_pass2_kernel() {
    __shared__ float2 sc[8][NCH];                      // [d_local][ch], 8 KB
    int b  = blockIdx.x >> 6;                          // 512 blocks
    int d0 = (blockIdx.x & 63) << 3;
    int t = threadIdx.x;
    for (int i = t; i < 8*NCH; i += 256) {
        int ch = i >> 3, dl = i & 7;
        sc[dl][ch] = g_carry[((size_t)b*NCH + ch)*DMODEL + d0 + dl];
    }
    __syncthreads();
    int w = t >> 5, lane = t & 31;
    float2 Ac = g_Ac[d0 + w];                          // A^32
    float2 c0 = sc[w][4*lane];
    float2 c1 = sc[w][4*lane+1];
    float2 c2 = sc[w][4*lane+2];
    float2 c3 = sc[w][4*lane+3];
    float2 v = cmad(Ac, cmad(Ac, cmad(Ac, c0, c1), c2), c3);
    float2 w2 = cmul(Ac, Ac);
    float2 wk = cmul(w2, w2);                          // Ac^4 per-group step
    #pragma unroll
    for (int off = 1; off < 32; off <<= 1) {
        float2 pv;
        pv.x = __shfl_up_sync(0xFFFFFFFFu, v.x, off);
        pv.y = __shfl_up_sync(0xFFFFFFFFu, v.y, off);
        if (lane >= off) v = cmad(wk, pv, v);
        wk = cmul(wk, wk);
    }
    float2 prev;
    prev.x = __shfl_up_sync(0xFFFFFFFFu, v.x, 1);
    prev.y = __shfl_up_sync(0xFFFFFFFFu, v.y, 1);
    if (lane == 0) prev = make_float2(0.f, 0.f);
    float2 e0 = prev;
    float2 e1 = cmad(Ac, e0, c0);
    float2 e2 = cmad(Ac, e1, c1);
    float2 e3 = cmad(Ac, e2, c2);
    sc[w][4*lane]   = e0;
    sc[w][4*lane+1] = e1;
    sc[w][4*lane+2] = e2;
    sc[w][4*lane+3] = e3;
    __syncthreads();
    for (int i = t; i < 8*NCH; i += 256) {
        int ch = i >> 3, dl = i & 7;
        g_carry[((size_t)b*NCH + ch)*DMODEL + d0 + dl] = sc[dl][ch];
    }
}

// ---------------- pass3: interleaved X2 store (one 8B STG per step) ----------
__global__ __launch_bounds__(256)
void scan_pass3_kernel(float2* __restrict__ xext, int use_ext, float* __restrict__ xreal) {
    int tid = blockIdx.x*blockDim.x + threadIdx.x;   // 262144 threads
    int dg = tid & 255;
    int ch = (tid >> 8) & (NCH-1);
    int b  = tid >> 15;
    if (b >= BATCH) return;
    int d = dg << 1;
    float2 A[2], x[2];
    #pragma unroll
    for (int q = 0; q < 2; q++) A[q] = g_A[d+q];
    {
        float4 c0 = *(const float4*)(g_carry + ((size_t)b*NCH + ch)*DMODEL + d);
        x[0] = make_float2(c0.x, c0.y);
        x[1] = make_float2(c0.z, c0.w);
    }
    int m0 = b*LSEQ + ch*CHUNK;
    size_t base = (size_t)m0*DMODEL + d;
    const __half2* up = g_u + base;
    float* xo = (float*)((use_ext ? xext : g_x) + base);
    #pragma unroll 8
    for (int s = 0; s < CHUNK; s++) {
        float2 raw = *(const float2*)up;
        const __half2* hp = (const __half2*)&raw;
        #pragma unroll
        for (int q = 0; q < 2; q++) {
            float2 u = __half22float2(hp[q]);
            x[q] = cmad(A[q], x[q], u);
        }
        stcs4(xo, make_float4(x[0].x, x[0].y, x[1].x, x[1].y));
        if (xreal)
            stcs2(xreal + base + (size_t)s*DMODEL, make_float2(x[0].x, x[1].x));
        // interleaved fp16 x: (re0,im0,re1,im1) -> 8B at xrow + 2d
        size_t xrow = (size_t)(m0 + s)*K2;
        __half2 h01 = __floats2half2_rn(x[0].x, x[0].y);
        __half2 h23 = __floats2half2_rn(x[1].x, x[1].y);
        uint2 pk;
        pk.x = *(uint32_t*)&h01;
        pk.y = *(uint32_t*)&h23;
        *(uint2*)(g_X2 + xrow + 2*d) = pk;
        up += DMODEL;
        xo += 2*DMODEL;
    }
}

// ---------------- host -------------------------------------------------------
extern "C" void kernel_launch(void* const* d_in, const int* in_sizes, int n_in,
                              void* d_out, int out_size) {
    const float* inputs    = (const float*)d_in[0];
    const float* nu_log    = (const float*)d_in[1];
    const float* theta_log = (const float*)d_in[2];
    const float* gamma_log = (const float*)d_in[3];
    const float* B_re      = (const float*)d_in[4];
    const float* B_im      = (const float*)d_in[5];
    const float* C_re      = (const float*)d_in[6];
    const float* C_im      = (const float*)d_in[7];
    const float* Dw        = (const float*)d_in[8];
    float* outF = (float*)d_out;

    const long long X = (long long)ML*DMODEL;
    const long long Y = (long long)ML*OUTDIM;
    float2* xext = 0; int use_ext = 0; float* xreal = 0;
    float* yout = 0; int pair = 0;
    long long os = (long long)out_size;
    if      (os == 2*X + Y)   { xext = (float2*)d_out; use_ext = 1; yout = outF + 2*X; }
    else if (os == 2*X + 2*Y) { xext = (float2*)d_out; use_ext = 1; yout = outF + 2*X; pair = 1; }
    else if (os == X + Y)     { xreal = outF; yout = outF + X; }
    else if (os == Y)         { yout = outF; }
    else if (os == 2*X)       { xext = (float2*)d_out; use_ext = 1; }
    else                      { xext = (float2*)d_out; use_ext = 1; yout = outF + 2*X; pair = 1; }

    cudaFuncSetAttribute(gemm_g1_kernel,
                         cudaFuncAttributeMaxDynamicSharedMemorySize, GEMM_SMEM);
    cudaFuncSetAttribute(gemm_g2_kernel,
                         cudaFuncAttributeMaxDynamicSharedMemorySize, GEMM64_SMEM);

    // fused preps: conv(4096) | W1(512) | W2(1280) | A(2)
    prep_all_kernel<<<5890, 256>>>(inputs, nu_log, theta_log, gamma_log,
                                   B_re, B_im, C_re, C_im, Dw);

    // G1: u = inputs x W1^T  (M=32768, N=1024, K=256)
    gemm_g1_kernel<<<dim3(1024/128, ML/128), 256, GEMM_SMEM>>>();

    scan_pass1_kernel<<<(BATCH*NCH*DMODEL/2)/256, 256>>>();
    scan_pass2_kernel<<<BATCH*DMODEL/8, 256>>>();
    scan_pass3_kernel<<<(BATCH*NCH*DMODEL/2)/256, 256>>>(xext, use_ext, xreal);

    if (yout) {
        // G2: y = [x_interleaved|inp] x [Cr/-Ci interleaved|D]^T, 64x64 tiles
        gemm_g2_kernel<<<dim3(256/64, ML/64), 256, GEMM64_SMEM>>>(yout, pair);
    }
}

// round 17
// speedup vs baseline: 1.0723x; 1.0265x over previous
#include <cuda_runtime.h>
#include <cuda_fp16.h>
#include <stdint.h>
#include <math.h>

#define BATCH   8
#define LSEQ    4096
#define INDIM   256
#define DMODEL  512
#define OUTDIM  256
#define ML      (BATCH*LSEQ)      /* 32768 */
#define CHUNK   32
#define NCH     (LSEQ/CHUNK)      /* 128 */
#define K2      1280              /* x interleaved re/im (1024) + inp(256) */
#define BK      32
#define PAD     40                /* padded smem row, fp16 elems (80 B) */
#define STAGES  4
#define ABYTES  (128*PAD*2)       /* 10240 B per operand tile (128-row) */
#define STG_BYTES (2*ABYTES)
#define GEMM_SMEM (STAGES*STG_BYTES)    /* 81920 B */
#define ABYTES64 (64*PAD*2)       /* 5120 B per operand tile (64-row) */
#define STG64    (2*ABYTES64)
#define GEMM64_SMEM (STAGES*STG64)      /* 40960 B */

// ---------------- device scratch -------------------------------------------
__device__ __align__(16) __half2 g_u[(size_t)ML*DMODEL];     // 64 MB (fp16 complex u)
__device__ __align__(16) float2 g_x[(size_t)ML*DMODEL];      // fallback
__device__ __align__(16) float2 g_carry[(size_t)BATCH*NCH*DMODEL];
__device__ float2 g_A[DMODEL];
__device__ float2 g_Ac[DMODEL];
__device__ __align__(16) __half g_X2[(size_t)ML*K2];         // 80 MB (fp16 activations)
__device__ __align__(16) __half g_W1[1024*256];              // fp16 weights
__device__ __align__(16) __half g_W2[256*K2];

__device__ __forceinline__ float2 cmul(float2 a, float2 b) {
    return make_float2(a.x*b.x - a.y*b.y, a.x*b.y + a.y*b.x);
}
__device__ __forceinline__ float2 cmad(float2 a, float2 b, float2 c) {
    return make_float2(fmaf(a.x, b.x, fmaf(-a.y, b.y, c.x)),
                       fmaf(a.x, b.y, fmaf( a.y, b.x, c.y)));
}

// ---------------- PTX helpers ------------------------------------------------
__device__ __forceinline__ uint32_t smem_u32(const void* p) {
    uint32_t a;
    asm("{ .reg .u64 t; cvta.to.shared.u64 t, %1; cvt.u32.u64 %0, t; }" : "=r"(a) : "l"(p));
    return a;
}
__device__ __forceinline__ void cp16(uint32_t dst, const void* src) {
    asm volatile("cp.async.cg.shared.global [%0], [%1], 16;" :: "r"(dst), "l"(src));
}
#define CP_COMMIT()  asm volatile("cp.async.commit_group;")
#define CP_WAIT2()   asm volatile("cp.async.wait_group 2;")
#define CP_WAIT0()   asm volatile("cp.async.wait_group 0;")

#define LDSM4(r, addr) \
    asm volatile("ldmatrix.sync.aligned.m8n8.x4.shared.b16 {%0,%1,%2,%3}, [%4];" \
        : "=r"((r)[0]),"=r"((r)[1]),"=r"((r)[2]),"=r"((r)[3]) : "r"(addr))

__device__ __forceinline__ void mma16816(float* c, const uint32_t* a, const uint32_t* b) {
    asm volatile("mma.sync.aligned.m16n8k16.row.col.f32.f16.f16.f32 "
        "{%0,%1,%2,%3}, {%4,%5,%6,%7}, {%8,%9}, {%0,%1,%2,%3};"
        : "+f"(c[0]), "+f"(c[1]), "+f"(c[2]), "+f"(c[3])
        : "r"(a[0]),"r"(a[1]),"r"(a[2]),"r"(a[3]), "r"(b[0]),"r"(b[1]));
}
__device__ __forceinline__ void stcs4(float* p, float4 v) {
    asm volatile("st.global.cs.v4.f32 [%0], {%1,%2,%3,%4};"
        :: "l"(p), "f"(v.x), "f"(v.y), "f"(v.z), "f"(v.w) : "memory");
}
__device__ __forceinline__ void stcs2(float* p, float2 v) {
    asm volatile("st.global.cs.v2.f32 [%0], {%1,%2};"
        :: "l"(p), "f"(v.x), "f"(v.y) : "memory");
}
__device__ __forceinline__ float2 ldcs2(const void* p) {
    float2 v;
    asm volatile("ld.global.cs.v2.f32 {%0,%1}, [%2];"
        : "=f"(v.x), "=f"(v.y) : "l"(p));
    return v;
}

// ---------------- fused prep: conv(4096) | W1(512) | W2(1280) | A(2) ---------
__global__ void prep_all_kernel(const float* __restrict__ inp,
                                const float* __restrict__ nu_log,
                                const float* __restrict__ theta_log,
                                const float* __restrict__ gamma_log,
                                const float* __restrict__ B_re,
                                const float* __restrict__ B_im,
                                const float* __restrict__ C_re,
                                const float* __restrict__ C_im,
                                const float* __restrict__ Dw) {
    int bid = blockIdx.x;
    int t = threadIdx.x;
    if (bid < 4096) {                                   // conv inputs -> X2 fp16
        int i = bid*256 + t;
        int m = i >> 5, h8 = (i & 31) << 3;
        const float4* src = (const float4*)(inp + (size_t)m*INDIM + h8);
        float4 v0 = src[0], v1 = src[1];
        float vals[8] = {v0.x, v0.y, v0.z, v0.w, v1.x, v1.y, v1.z, v1.w};
        __half hv[8];
        #pragma unroll
        for (int j = 0; j < 8; j++) hv[j] = __float2half_rn(vals[j]);
        *(uint4*)(g_X2 + (size_t)m*K2 + 1024 + h8) = *(uint4*)hv;
    } else if (bid < 4096 + 512) {                      // W1
        int i = (bid - 4096)*256 + t;                   // d*256 + h
        int d = i >> 8, h = i & 255;
        float s = expf(gamma_log[d]);
        g_W1[(size_t)(2*d)*256   + h] = __float2half_rn(B_re[i]*s);
        g_W1[(size_t)(2*d+1)*256 + h] = __float2half_rn(B_im[i]*s);
    } else if (bid < 4096 + 512 + 1280) {               // W2 (x part INTERLEAVED)
        int i = (bid - 4608)*256 + t;                   // n*K2 + k
        int n = i / K2, k = i % K2;
        float v;
        if (k < 1024) {                                 // interleaved Cr/-Ci
            int j = k >> 1;
            v = (k & 1) ? -C_im[(size_t)n*512 + j] : C_re[(size_t)n*512 + j];
        } else {
            v = Dw[(size_t)n*256 + (k-1024)];
        }
        g_W2[i] = __float2half_rn(v);
    } else {                                            // A
        int d = (bid - 5888)*256 + t;
        if (d >= DMODEL) return;
        float r  = expf(-expf(nu_log[d]));
        float th = expf(theta_log[d]);
        float2 A = make_float2(r*cosf(th), r*sinf(th));
        g_A[d] = A;
        float2 p = make_float2(1.f, 0.f);
        #pragma unroll 8
        for (int i2 = 0; i2 < CHUNK; i2++) p = cmul(p, A);
        g_Ac[d] = p;                                    // A^CHUNK = A^32
    }
}

// ---------------- G1: 128x128 tiles, u = inputs x W1^T ----------------------
__device__ __forceinline__ void issue_loads128(
    int t, uint32_t sbase, int stg, int c,
    const __half* Aw, long lda,
    const __half* Bw, long ldb,
    int mBase, int nBase)
{
    long koff = (long)c * BK;
    uint32_t aBuf = sbase + stg*STG_BYTES;
    uint32_t bBuf = aBuf + ABYTES;
    #pragma unroll
    for (int r = 0; r < 2; r++) {
        int ci = t + r*256; int row = ci >> 2, j = ci & 3;
        cp16(aBuf + row*(PAD*2) + j*16, Aw + (size_t)(mBase+row)*lda + koff + j*8);
        cp16(bBuf + row*(PAD*2) + j*16, Bw + (size_t)(nBase+row)*ldb + koff + j*8);
    }
    CP_COMMIT();
}

__global__ __launch_bounds__(256, 2)
void gemm_g1_kernel() {
    const __half* Aw = g_X2 + 1024;  const long lda = K2;
    const __half* Bw = g_W1;         const long ldb = 256;
    const int NC = 256 / BK;         // 8
    const int t = threadIdx.x;
    const int wid = t >> 5, lane = t & 31;
    const int warp_m = wid & 3, warp_n = wid >> 2;
    const int mBase = blockIdx.y * 128;
    const int nBase = blockIdx.x * 128;

    extern __shared__ __align__(16) char smem[];
    uint32_t sbase = smem_u32(smem);

    float acc[2][8][4];
    #pragma unroll
    for (int mi = 0; mi < 2; mi++)
        #pragma unroll
        for (int ni = 0; ni < 8; ni++)
            #pragma unroll
            for (int q = 0; q < 4; q++) acc[mi][ni][q] = 0.f;

    uint32_t a_off[2], b_off[4];
    #pragma unroll
    for (int mi = 0; mi < 2; mi++) {
        int row = warp_m*32 + mi*16 + (lane & 15);
        int col = (lane >> 4) << 3;
        a_off[mi] = (uint32_t)((row*PAD + col) * 2);
    }
    #pragma unroll
    for (int p = 0; p < 4; p++) {
        int nrow = warp_n*64 + p*16 + (lane & 7) + ((lane >> 4) << 3);
        int col  = ((lane >> 3) & 1) << 3;
        b_off[p] = (uint32_t)((nrow*PAD + col) * 2);
    }

    issue_loads128(t, sbase, 0, 0, Aw, lda, Bw, ldb, mBase, nBase);
    issue_loads128(t, sbase, 1, 1, Aw, lda, Bw, ldb, mBase, nBase);
    issue_loads128(t, sbase, 2, 2, Aw, lda, Bw, ldb, mBase, nBase);

    for (int c = 0; c < NC; c++) {
        int stg = c & 3;
        CP_WAIT2();
        __syncthreads();
        if (c + 3 < NC)
            issue_loads128(t, sbase, (c+3) & 3, c+3, Aw, lda, Bw, ldb, mBase, nBase);
        else
            CP_COMMIT();

        uint32_t baseA = sbase + stg*STG_BYTES, baseB = baseA + ABYTES;
        #pragma unroll
        for (int ks = 0; ks < 2; ks++) {
            uint32_t afr[2][4], bfr[4][4];
            #pragma unroll
            for (int mi = 0; mi < 2; mi++) LDSM4(afr[mi], baseA + a_off[mi] + ks*32);
            #pragma unroll
            for (int p = 0; p < 4; p++)    LDSM4(bfr[p],  baseB + b_off[p]  + ks*32);
            #pragma unroll
            for (int mi = 0; mi < 2; mi++)
                #pragma unroll
                for (int ni = 0; ni < 8; ni++)
                    mma16816(acc[mi][ni], afr[mi], &bfr[ni >> 1][(ni & 1) * 2]);
        }
    }
    CP_WAIT0();

    // u epilogue: fp16 complex (half2 per element)
    #pragma unroll
    for (int mi = 0; mi < 2; mi++) {
        int r0 = mBase + warp_m*32 + mi*16 + (lane >> 2);
        #pragma unroll
        for (int ni = 0; ni < 8; ni++) {
            int col = nBase + warp_n*64 + ni*8 + (lane & 3)*2;   // even
            g_u[(size_t)r0*DMODEL + (col >> 1)] =
                __floats2half2_rn(acc[mi][ni][0], acc[mi][ni][1]);
            g_u[(size_t)(r0+8)*DMODEL + (col >> 1)] =
                __floats2half2_rn(acc[mi][ni][2], acc[mi][ni][3]);
        }
    }
}

// ---------------- G2: 64x64 tiles, f32-accum mma ----------------------------
__device__ __forceinline__ void issue_loads64(
    int t, uint32_t sbase, int stg, int c,
    int mBase, int nBase)
{
    long koff = (long)c * BK;
    uint32_t aBuf = sbase + stg*STG64;
    uint32_t bBuf = aBuf + ABYTES64;
    int row = t >> 2, j = t & 3;
    cp16(aBuf + row*(PAD*2) + j*16, g_X2 + (size_t)(mBase+row)*K2 + koff + j*8);
    cp16(bBuf + row*(PAD*2) + j*16, g_W2 + (size_t)(nBase+row)*K2 + koff + j*8);
    CP_COMMIT();
}

__global__ __launch_bounds__(256, 2)
void gemm_g2_kernel(float* __restrict__ yout, int pair) {
    const int NC = K2 / BK;          // 40
    const int t = threadIdx.x;
    const int wid = t >> 5, lane = t & 31;
    const int warp_m = wid & 3, warp_n = wid >> 2;   // warp tile 16x32
    const int mBase = blockIdx.y * 64;
    const int nBase = blockIdx.x * 64;

    extern __shared__ __align__(16) char smem[];
    uint32_t sbase = smem_u32(smem);

    float acc[4][4];
    #pragma unroll
    for (int ni = 0; ni < 4; ni++)
        #pragma unroll
        for (int q = 0; q < 4; q++) acc[ni][q] = 0.f;

    uint32_t a_off, b_off[2];
    {
        int row = warp_m*16 + (lane & 15);
        int col = (lane >> 4) << 3;
        a_off = (uint32_t)((row*PAD + col) * 2);
    }
    #pragma unroll
    for (int p = 0; p < 2; p++) {
        int nrow = warp_n*32 + p*16 + (lane & 7) + ((lane >> 4) << 3);
        int col  = ((lane >> 3) & 1) << 3;
        b_off[p] = (uint32_t)((nrow*PAD + col) * 2);
    }

    issue_loads64(t, sbase, 0, 0, mBase, nBase);
    issue_loads64(t, sbase, 1, 1, mBase, nBase);
    issue_loads64(t, sbase, 2, 2, mBase, nBase);

    for (int c = 0; c < NC; c++) {
        int stg = c & 3;
        CP_WAIT2();
        __syncthreads();
        if (c + 3 < NC)
            issue_loads64(t, sbase, (c+3) & 3, c+3, mBase, nBase);
        else
            CP_COMMIT();

        uint32_t baseA = sbase + stg*STG64, baseB = baseA + ABYTES64;
        #pragma unroll
        for (int ks = 0; ks < 2; ks++) {
            uint32_t afr[4], bfr[2][4];
            LDSM4(afr, baseA + a_off + ks*32);
            #pragma unroll
            for (int p = 0; p < 2; p++) LDSM4(bfr[p], baseB + b_off[p] + ks*32);
            #pragma unroll
            for (int ni = 0; ni < 4; ni++)
                mma16816(acc[ni], afr, &bfr[ni >> 1][(ni & 1) * 2]);
        }
    }
    CP_WAIT0();

    int r0 = mBase + warp_m*16 + (lane >> 2);
    if (pair) {
        #pragma unroll
        for (int ni = 0; ni < 4; ni++) {
            int col = nBase + warp_n*32 + ni*8 + (lane & 3)*2;
            *(float4*)(yout + 2*((size_t)r0*256 + col)) =
                make_float4(acc[ni][0], 0.f, acc[ni][1], 0.f);
            *(float4*)(yout + 2*((size_t)(r0+8)*256 + col)) =
                make_float4(acc[ni][2], 0.f, acc[ni][3], 0.f);
        }
    } else {
        #pragma unroll
        for (int ni = 0; ni < 4; ni++) {
            int col = nBase + warp_n*32 + ni*8 + (lane & 3)*2;
            *(float2*)(yout + (size_t)r0*256 + col)     = make_float2(acc[ni][0], acc[ni][1]);
            *(float2*)(yout + (size_t)(r0+8)*256 + col) = make_float2(acc[ni][2], acc[ni][3]);
        }
    }
}

// ---------------- chunked parallel scan (2 d's per thread) -------------------
__global__ __launch_bounds__(256)
void scan_pass1_kernel() {
    int tid = blockIdx.x*blockDim.x + threadIdx.x;   // 262144 threads
    int dg = tid & 255;
    int ch = (tid >> 8) & (NCH-1);
    int b  = tid >> 15;
    if (b >= BATCH) return;
    int d = dg << 1;
    float2 A[2], x[2];
    #pragma unroll
    for (int q = 0; q < 2; q++) { A[q] = g_A[d+q]; x[q] = make_float2(0.f, 0.f); }
    const __half2* up = g_u + ((size_t)(b*LSEQ + ch*CHUNK))*DMODEL + d;
    #pragma unroll 8
    for (int s = 0; s < CHUNK; s++) {
        float2 raw = *(const float2*)up;             // 2 half2 complexes (8B)
        const __half2* hp = (const __half2*)&raw;
        #pragma unroll
        for (int q = 0; q < 2; q++) {
            float2 u = __half22float2(hp[q]);
            x[q] = cmad(A[q], x[q], u);
        }
        up += DMODEL;
    }
    *(float4*)(g_carry + ((size_t)b*NCH + ch)*DMODEL + d) =
        make_float4(x[0].x, x[0].y, x[1].x, x[1].y);
}

// ---------------- pass2: smem-staged Kogge-Stone, 16 d per 512-thr block -----
__global__ __launch_bounds__(512)
void scan_pass2_kernel() {
    __shared__ float2 sc[16][NCH + 1];                 // padded vs bank conflicts
    int b  = blockIdx.x >> 5;                          // 256 blocks
    int d0 = (blockIdx.x & 31) << 4;
    int t = threadIdx.x;
    for (int i = t; i < 16*NCH; i += 512) {
        int ch = i >> 4, dl = i & 15;
        sc[dl][ch] = g_carry[((size_t)b*NCH + ch)*DMODEL + d0 + dl];
    }
    __syncthreads();
    int w = t >> 5, lane = t & 31;
    float2 Ac = g_Ac[d0 + w];                          // A^32
    float2 c0 = sc[w][4*lane];
    float2 c1 = sc[w][4*lane+1];
    float2 c2 = sc[w][4*lane+2];
    float2 c3 = sc[w][4*lane+3];
    float2 v = cmad(Ac, cmad(Ac, cmad(Ac, c0, c1), c2), c3);
    float2 w2 = cmul(Ac, Ac);
    float2 wk = cmul(w2, w2);                          // Ac^4 per-group step
    #pragma unroll
    for (int off = 1; off < 32; off <<= 1) {
        float2 pv;
        pv.x = __shfl_up_sync(0xFFFFFFFFu, v.x, off);
        pv.y = __shfl_up_sync(0xFFFFFFFFu, v.y, off);
        if (lane >= off) v = cmad(wk, pv, v);
        wk = cmul(wk, wk);
    }
    float2 prev;
    prev.x = __shfl_up_sync(0xFFFFFFFFu, v.x, 1);
    prev.y = __shfl_up_sync(0xFFFFFFFFu, v.y, 1);
    if (lane == 0) prev = make_float2(0.f, 0.f);
    float2 e0 = prev;
    float2 e1 = cmad(Ac, e0, c0);
    float2 e2 = cmad(Ac, e1, c1);
    float2 e3 = cmad(Ac, e2, c2);
    sc[w][4*lane]   = e0;
    sc[w][4*lane+1] = e1;
    sc[w][4*lane+2] = e2;
    sc[w][4*lane+3] = e3;
    __syncthreads();
    for (int i = t; i < 16*NCH; i += 512) {
        int ch = i >> 4, dl = i & 15;
        g_carry[((size_t)b*NCH + ch)*DMODEL + d0 + dl] = sc[dl][ch];
    }
}

// ---------------- pass3: last-use u reads streamed, interleaved X2 store -----
__global__ __launch_bounds__(256)
void scan_pass3_kernel(float2* __restrict__ xext, int use_ext, float* __restrict__ xreal) {
    int tid = blockIdx.x*blockDim.x + threadIdx.x;   // 262144 threads
    int dg = tid & 255;
    int ch = (tid >> 8) & (NCH-1);
    int b  = tid >> 15;
    if (b >= BATCH) return;
    int d = dg << 1;
    float2 A[2], x[2];
    #pragma unroll
    for (int q = 0; q < 2; q++) A[q] = g_A[d+q];
    {
        float4 c0 = *(const float4*)(g_carry + ((size_t)b*NCH + ch)*DMODEL + d);
        x[0] = make_float2(c0.x, c0.y);
        x[1] = make_float2(c0.z, c0.w);
    }
    int m0 = b*LSEQ + ch*CHUNK;
    size_t base = (size_t)m0*DMODEL + d;
    const __half2* up = g_u + base;
    float* xo = (float*)((use_ext ? xext : g_x) + base);
    #pragma unroll 8
    for (int s = 0; s < CHUNK; s++) {
        float2 raw = ldcs2(up);                      // last use of u: evict-first
        const __half2* hp = (const __half2*)&raw;
        #pragma unroll
        for (int q = 0; q < 2; q++) {
            float2 u = __half22float2(hp[q]);
            x[q] = cmad(A[q], x[q], u);
        }
        stcs4(xo, make_float4(x[0].x, x[0].y, x[1].x, x[1].y));
        if (xreal)
            stcs2(xreal + base + (size_t)s*DMODEL, make_float2(x[0].x, x[1].x));
        // interleaved fp16 x: (re0,im0,re1,im1) -> 8B at xrow + 2d
        size_t xrow = (size_t)(m0 + s)*K2;
        __half2 h01 = __floats2half2_rn(x[0].x, x[0].y);
        __half2 h23 = __floats2half2_rn(x[1].x, x[1].y);
        uint2 pk;
        pk.x = *(uint32_t*)&h01;
        pk.y = *(uint32_t*)&h23;
        *(uint2*)(g_X2 + xrow + 2*d) = pk;
        up += DMODEL;
        xo += 2*DMODEL;
    }
}

// ---------------- host -------------------------------------------------------
extern "C" void kernel_launch(void* const* d_in, const int* in_sizes, int n_in,
                              void* d_out, int out_size) {
    const float* inputs    = (const float*)d_in[0];
    const float* nu_log    = (const float*)d_in[1];
    const float* theta_log = (const float*)d_in[2];
    const float* gamma_log = (const float*)d_in[3];
    const float* B_re      = (const float*)d_in[4];
    const float* B_im      = (const float*)d_in[5];
    const float* C_re      = (const float*)d_in[6];
    const float* C_im      = (const float*)d_in[7];
    const float* Dw        = (const float*)d_in[8];
    float* outF = (float*)d_out;

    const long long X = (long long)ML*DMODEL;
    const long long Y = (long long)ML*OUTDIM;
    float2* xext = 0; int use_ext = 0; float* xreal = 0;
    float* yout = 0; int pair = 0;
    long long os = (long long)out_size;
    if      (os == 2*X + Y)   { xext = (float2*)d_out; use_ext = 1; yout = outF + 2*X; }
    else if (os == 2*X + 2*Y) { xext = (float2*)d_out; use_ext = 1; yout = outF + 2*X; pair = 1; }
    else if (os == X + Y)     { xreal = outF; yout = outF + X; }
    else if (os == Y)         { yout = outF; }
    else if (os == 2*X)       { xext = (float2*)d_out; use_ext = 1; }
    else                      { xext = (float2*)d_out; use_ext = 1; yout = outF + 2*X; pair = 1; }

    cudaFuncSetAttribute(gemm_g1_kernel,
                         cudaFuncAttributeMaxDynamicSharedMemorySize, GEMM_SMEM);
    cudaFuncSetAttribute(gemm_g2_kernel,
                         cudaFuncAttributeMaxDynamicSharedMemorySize, GEMM64_SMEM);

    // fused preps: conv(4096) | W1(512) | W2(1280) | A(2)
    prep_all_kernel<<<5890, 256>>>(inputs, nu_log, theta_log, gamma_log,
                                   B_re, B_im, C_re, C_im, Dw);

    // G1: u = inputs x W1^T  (M=32768, N=1024, K=256)
    gemm_g1_kernel<<<dim3(1024/128, ML/128), 256, GEMM_SMEM>>>();

    scan_pass1_kernel<<<(BATCH*NCH*DMODEL/2)/256, 256>>>();
    scan_pass2_kernel<<<BATCH*DMODEL/16, 512>>>();
    scan_pass3_kernel<<<(BATCH*NCH*DMODEL/2)/256, 256>>>(xext, use_ext, xreal);

    if (yout) {
        // G2: y = [x_interleaved|inp] x [Cr/-Ci interleaved|D]^T, 64x64 tiles
        gemm_g2_kernel<<<dim3(256/64, ML/64), 256, GEMM64_SMEM>>>(yout, pair);
    }
}